// round 2
// baseline (speedup 1.0000x reference)
#include <cuda_runtime.h>
#include <math.h>

#define N1 6001
#define DD 64
#define LL 200
#define BB 32
#define PP (BB*LL)      // 6400
#define QT 32
#define KC 64
#define MAXNZ 1024

// ---------------- device scratch (zero-initialized at load) ----------------
__device__ __align__(16) float g_h[N1*DD];
__device__ float g_wh1[N1];
__device__ float g_wh2[N1];
__device__ __align__(16) float g_hmean[DD];
__device__ int   g_flags[N1];
__device__ __align__(16) float g_gat_i[N1*DD];
__device__ __align__(16) float g_trans_i[N1*DD];
__device__ __align__(16) float g_seqs_i[N1*DD];
__device__ __align__(16) float g_A1[N1*DD];
__device__ __align__(16) float g_A2[N1*DD];
__device__ __align__(16) float g_P1[LL*DD];
__device__ __align__(16) float g_P2[LL*DD];
__device__ __align__(16) float g_E1[PP*DD];
__device__ __align__(16) float g_E2[PP*DD];
__device__ __align__(16) float g_final[PP*DD];

__device__ __forceinline__ float fast_rcp(float u){
    // u >= 1 here. Bit-hack + 2 Newton: rel err ~1e-6, pure FMA/ALU (no MUFU).
    float y = __int_as_float(0x7EF311C3 - __float_as_int(u));
    y = y * (2.0f - u*y);
    y = y * (2.0f - u*y);
    return y;
}

// ---------------- K0: flags ----------------
__global__ void k0_clear(){
    int i = blockIdx.x*256 + threadIdx.x;
    if (i < N1) g_flags[i] = 0;
}
__global__ void k0_mark(const int* __restrict__ logs){
    int p = blockIdx.x*256 + threadIdx.x;
    if (p < PP) g_flags[logs[p]] = 1;
}

// ---------------- K1: h = emb @ W_item ; wh1/wh2 (register-tiled) ----------------
__global__ void k1_hitem(const float* __restrict__ emb, const float* __restrict__ Wi,
                         const float* __restrict__ ai){
    __shared__ float Ws[4096];
    __shared__ float Xs[1024];
    __shared__ float as_[128];
    int t = threadIdx.x;
    for (int u=t; u<1024; u+=256) ((float4*)Ws)[u] = ((const float4*)Wi)[u];
    if (t < 32) ((float4*)as_)[t] = ((const float4*)ai)[t];
    int r0 = blockIdx.x*16;
    {
        int row = t>>4, col = t&15;
        int r = r0 + row;
        float4 v = make_float4(0.f,0.f,0.f,0.f);
        if (r < N1) v = ((const float4*)(emb + r*DD))[col];
        ((float4*)Xs)[t] = v;
    }
    __syncthreads();
    int tp = t>>4, dq = t&15;
    float4 acc = make_float4(0.f,0.f,0.f,0.f);
    const float* xr = Xs + tp*DD;
    #pragma unroll
    for (int k=0;k<DD;k++){
        float xv = xr[k];
        float4 w = ((float4*)Ws)[k*16+dq];
        acc.x=fmaf(xv,w.x,acc.x); acc.y=fmaf(xv,w.y,acc.y);
        acc.z=fmaf(xv,w.z,acc.z); acc.w=fmaf(xv,w.w,acc.w);
    }
    int r = r0 + tp;
    if (r < N1) ((float4*)(g_h + r*DD))[dq] = acc;
    float4 a1=((float4*)as_)[dq], a2=((float4*)as_)[16+dq];
    float s1 = acc.x*a1.x+acc.y*a1.y+acc.z*a1.z+acc.w*a1.w;
    float s2 = acc.x*a2.x+acc.y*a2.y+acc.z*a2.z+acc.w*a2.w;
    #pragma unroll
    for (int o=8;o>0;o>>=1){
        s1 += __shfl_xor_sync(0xffffffffu, s1, o);
        s2 += __shfl_xor_sync(0xffffffffu, s2, o);
    }
    if (dq==0 && r<N1){ g_wh1[r]=s1; g_wh2[r]=s2; }
}

// ---------------- K1b: column mean of h (fallback for empty adj rows) ----------------
__global__ void k1b_hmean(){
    int b = blockIdx.x; int t = threadIdx.x;
    float4 s = make_float4(0.f,0.f,0.f,0.f);
    for (int r=t; r<N1; r+=256){
        float4 v = ((float4*)g_h)[r*16+b];
        s.x+=v.x; s.y+=v.y; s.z+=v.z; s.w+=v.w;
    }
    __shared__ float4 red[256];
    red[t]=s; __syncthreads();
    for (int o=128;o>0;o>>=1){
        if (t<o){ float4 a=red[t], c=red[t+o]; a.x+=c.x;a.y+=c.y;a.z+=c.z;a.w+=c.w; red[t]=a; }
        __syncthreads();
    }
    if (t==0){
        float4 a=red[0]; float inv=1.f/(float)N1;
        ((float4*)g_hmean)[b]=make_float4(a.x*inv,a.y*inv,a.z*inv,a.w*inv);
    }
}

// ---------------- K1c: P1 = pe@W1, P2 = pe@W2 ----------------
__global__ void k1c_pproj(const float* __restrict__ pe, const float* __restrict__ w1g,
                          const float* __restrict__ w2g){
    __shared__ float W1s[4096], W2s[4096], Xs[1024];
    int t=threadIdx.x;
    for (int u=t;u<1024;u+=256){
        ((float4*)W1s)[u]=((const float4*)w1g)[u];
        ((float4*)W2s)[u]=((const float4*)w2g)[u];
    }
    int l0 = blockIdx.x*16;
    {
        int row=t>>4, col=t&15; int l=l0+row;
        float4 v = make_float4(0.f,0.f,0.f,0.f);
        if (l<LL) v = ((const float4*)(pe + l*DD))[col];
        ((float4*)Xs)[t]=v;
    }
    __syncthreads();
    int tp=t>>4, dq=t&15;
    float4 a1=make_float4(0.f,0.f,0.f,0.f), a2=a1;
    const float* xr = Xs + tp*DD;
    #pragma unroll
    for (int k=0;k<DD;k++){
        float xv=xr[k];
        float4 w1=((float4*)W1s)[k*16+dq], w2=((float4*)W2s)[k*16+dq];
        a1.x=fmaf(xv,w1.x,a1.x); a1.y=fmaf(xv,w1.y,a1.y); a1.z=fmaf(xv,w1.z,a1.z); a1.w=fmaf(xv,w1.w,a1.w);
        a2.x=fmaf(xv,w2.x,a2.x); a2.y=fmaf(xv,w2.y,a2.y); a2.z=fmaf(xv,w2.z,a2.z); a2.w=fmaf(xv,w2.w,a2.w);
    }
    int l=l0+tp;
    if (l<LL){ ((float4*)(g_P1+l*DD))[dq]=a1; ((float4*)(g_P2+l*DD))[dq]=a2; }
}

// ---------------- K2a: sparse GAT per UNIQUE item ----------------
__global__ void k2a_gat(const float* __restrict__ adj){
    __shared__ int   s_idx[MAXNZ];
    __shared__ float s_val[MAXNZ];
    __shared__ float s_e[MAXNZ];
    __shared__ int wsum[8]; __shared__ int woff[8]; __shared__ int s_n;
    __shared__ float wred[8];
    __shared__ float pg[4][DD], pt[4][DD];
    int i = blockIdx.x;
    if (g_flags[i]==0) return;
    int t=threadIdx.x, lane=t&31, w=t>>5;
    const float* row = adj + (size_t)i*(size_t)N1;
    int c=0;
    for (int j=t;j<N1;j+=256) c += (row[j]>0.f)?1:0;
    int sc=c;
    #pragma unroll
    for (int o=1;o<32;o<<=1){ int v=__shfl_up_sync(0xffffffffu,sc,o); if(lane>=o) sc+=v; }
    if (lane==31) wsum[w]=sc;
    __syncthreads();
    if (t<8){
        int v=wsum[t]; int iv=v;
        #pragma unroll
        for (int o=1;o<8;o<<=1){ int u=__shfl_up_sync(0x000000ffu,iv,o); if(t>=o) iv+=u; }
        woff[t]=iv-v;
        if (t==7) s_n=iv;
    }
    __syncthreads();
    int off = woff[w] + (sc - c);
    for (int j=t;j<N1;j+=256){
        float a=row[j];
        if (a>0.f){ if(off<MAXNZ){ s_idx[off]=j; s_val[off]=a; } off++; }
    }
    __syncthreads();
    int n = s_n; if (n>MAXNZ) n=MAXNZ;
    float wh1i = g_wh1[i];
    float m=-1e30f;
    for (int k=t;k<n;k+=256){
        float e = wh1i + g_wh2[s_idx[k]];
        e = (e>0.f)? e : 0.01f*e;
        s_e[k]=e;
        m = fmaxf(m,e);
    }
    #pragma unroll
    for (int o=16;o>0;o>>=1) m=fmaxf(m,__shfl_xor_sync(0xffffffffu,m,o));
    if (lane==0) wred[w]=m;
    __syncthreads();
    float M=wred[0];
    #pragma unroll
    for (int k=1;k<8;k++) M=fmaxf(M,wred[k]);
    __syncthreads();
    float ds=0.f;
    for (int k=t;k<n;k+=256){
        float wv=__expf(s_e[k]-M);
        s_e[k]=wv; ds+=wv;
    }
    #pragma unroll
    for (int o=16;o>0;o>>=1) ds += __shfl_xor_sync(0xffffffffu,ds,o);
    if (lane==0) wred[w]=ds;
    __syncthreads();
    float den=0.f;
    #pragma unroll
    for (int k=0;k<8;k++) den+=wred[k];
    int d=t&63, g4=t>>6;
    float ga=0.f, ta=0.f;
    for (int k=g4;k<n;k+=4){
        float hv = g_h[s_idx[k]*DD+d];
        ga = fmaf(s_e[k],hv,ga);
        ta = fmaf(s_val[k],hv,ta);
    }
    pg[g4][d]=ga; pt[g4][d]=ta;
    __syncthreads();
    if (t<DD){
        float gg=(pg[0][t]+pg[1][t])+(pg[2][t]+pg[3][t]);
        float tt=(pt[0][t]+pt[1][t])+(pt[2][t]+pt[3][t]);
        if (n>0){ g_gat_i[i*DD+t]=gg/den; g_trans_i[i*DD+t]=tt; }
        else    { g_gat_i[i*DD+t]=g_hmean[t]; g_trans_i[i*DD+t]=0.f; }
    }
}

// ---------------- K2b_item: per-item coff/seqs + A1/A2 projections ----------------
__global__ __launch_bounds__(256) void k2b_item(const float* __restrict__ emb,
        const float* __restrict__ ccg, const float* __restrict__ cng,
        const float* __restrict__ w1g, const float* __restrict__ w2g){
    extern __shared__ float sm[];
    float* CC=sm; float* CN=sm+4096; float* W1s=sm+8192; float* W2s=sm+12288;
    float* Xg=sm+16384; float* Xt=Xg+1024; float* Xe=Xt+1024; float* X2=Xe+1024;
    int t=threadIdx.x;
    for (int u=t;u<1024;u+=256){
        ((float4*)CC)[u]=((const float4*)ccg)[u];
        ((float4*)CN)[u]=((const float4*)cng)[u];
        ((float4*)W1s)[u]=((const float4*)w1g)[u];
        ((float4*)W2s)[u]=((const float4*)w2g)[u];
    }
    int r0=blockIdx.x*16;
    {
        int row=t>>4, col=t&15; int r=r0+row;
        float4 g=make_float4(0.f,0.f,0.f,0.f), tv=g, e=g;
        if (r<N1){
            g =((float4*)g_gat_i)[r*16+col];
            tv=((float4*)g_trans_i)[r*16+col];
            e =((const float4*)(emb))[r*16+col];
        }
        ((float4*)Xg)[t]=g; ((float4*)Xt)[t]=tv; ((float4*)Xe)[t]=e;
    }
    __syncthreads();
    int tp=t>>4, dq=t&15;
    float4 x=make_float4(0.f,0.f,0.f,0.f);
    const float* gr=Xg+tp*DD; const float* trr=Xt+tp*DD;
    #pragma unroll
    for (int k=0;k<DD;k++){
        float gv=gr[k], tv=trr[k];
        float4 c1=((float4*)CC)[k*16+dq], c2=((float4*)CN)[k*16+dq];
        x.x=fmaf(gv,c1.x,fmaf(tv,c2.x,x.x));
        x.y=fmaf(gv,c1.y,fmaf(tv,c2.y,x.y));
        x.z=fmaf(gv,c1.z,fmaf(tv,c2.z,x.z));
        x.w=fmaf(gv,c1.w,fmaf(tv,c2.w,x.w));
    }
    float4 cf;
    cf.x=fast_rcp(1.f+__expf(-x.x));
    cf.y=fast_rcp(1.f+__expf(-x.y));
    cf.z=fast_rcp(1.f+__expf(-x.z));
    cf.w=fast_rcp(1.f+__expf(-x.w));
    float4 g4=((float4*)Xg)[tp*16+dq], t4=((float4*)Xt)[tp*16+dq], e4=((float4*)Xe)[tp*16+dq];
    float4 sv;
    sv.x=cf.x*g4.x+(1.f-cf.x)*t4.x+e4.x;
    sv.y=cf.y*g4.y+(1.f-cf.y)*t4.y+e4.y;
    sv.z=cf.z*g4.z+(1.f-cf.z)*t4.z+e4.z;
    sv.w=cf.w*g4.w+(1.f-cf.w)*t4.w+e4.w;
    ((float4*)X2)[tp*16+dq]=sv;
    int r=r0+tp;
    if (r<N1) ((float4*)g_seqs_i)[r*16+dq]=sv;
    __syncthreads();
    float4 a1=make_float4(0.f,0.f,0.f,0.f), a2=a1;
    const float* x2r=X2+tp*DD;
    #pragma unroll
    for (int k=0;k<DD;k++){
        float xv=x2r[k];
        float4 w1=((float4*)W1s)[k*16+dq], w2=((float4*)W2s)[k*16+dq];
        a1.x=fmaf(xv,w1.x,a1.x); a1.y=fmaf(xv,w1.y,a1.y); a1.z=fmaf(xv,w1.z,a1.z); a1.w=fmaf(xv,w1.w,a1.w);
        a2.x=fmaf(xv,w2.x,a2.x); a2.y=fmaf(xv,w2.y,a2.y); a2.z=fmaf(xv,w2.z,a2.z); a2.w=fmaf(xv,w2.w,a2.w);
    }
    if (r<N1){ ((float4*)g_A1)[r*16+dq]=a1; ((float4*)g_A2)[r*16+dq]=a2; }
}

// ---------------- K2b_pos: E1 = exp(-(A1[i]+m*P1[l])), E2 likewise ----------------
__global__ void k2b_pos(const int* __restrict__ logs){
    int gi = blockIdx.x*256 + threadIdx.x;   // 102400 total
    int p = gi>>4, dq = gi&15;
    int i = logs[p];
    int l = p % LL;
    float m = (i!=0)? 1.f : 0.f;
    float4 a=((float4*)g_A1)[i*16+dq], q1=((float4*)g_P1)[l*16+dq];
    float4 e;
    e.x=__expf(-fmaf(m,q1.x,a.x));
    e.y=__expf(-fmaf(m,q1.y,a.y));
    e.z=__expf(-fmaf(m,q1.z,a.z));
    e.w=__expf(-fmaf(m,q1.w,a.w));
    ((float4*)g_E1)[gi]=e;
    a=((float4*)g_A2)[i*16+dq]; q1=((float4*)g_P2)[l*16+dq];
    e.x=__expf(-fmaf(m,q1.x,a.x));
    e.y=__expf(-fmaf(m,q1.y,a.y));
    e.z=__expf(-fmaf(m,q1.z,a.z));
    e.w=__expf(-fmaf(m,q1.w,a.w));
    ((float4*)g_E2)[gi]=e;
}

// ---------------- K3: score (sigmoid via FMA rcp) + causal attend, chunked ----------------
__global__ __launch_bounds__(256,2) void k3_attn(const float* __restrict__ ba,
                                                 const int* __restrict__ logs){
    __shared__ float E2c[KC*DD];
    __shared__ float Sc[KC*DD];
    __shared__ float scc[QT*KC];
    __shared__ int litem[KC];
    const int perm[7]={5,0,3,2,4,1,6};  // pair heavy/light tiles across +1 SM-placement step
    int t=threadIdx.x;
    int bb=blockIdx.y;
    int q0=perm[blockIdx.x]*QT;
    int qi=t>>3; int dh=(t>>2)&1; int kg=t&3; int dg=t&7;
    int q=q0+qi;
    float4 e1r[8], br[8];
    {
        const float4* baf=(const float4*)ba;
        #pragma unroll
        for (int j=0;j<8;j++) br[j]=baf[dh*8+j];
        if (q<LL){
            const float4* e1p=((const float4*)g_E1)+(size_t)(bb*LL+q)*16+dh*8;
            #pragma unroll
            for (int j=0;j<8;j++) e1r[j]=e1p[j];
        } else {
            #pragma unroll
            for (int j=0;j<8;j++) e1r[j]=make_float4(0.f,0.f,0.f,0.f);
        }
    }
    float4 ac0=make_float4(0.f,0.f,0.f,0.f), ac1=ac0;
    int kend=q0+QT; if (kend>LL) kend=LL;
    for (int kbase=0; kbase<kend; kbase+=KC){
        int rows=kend-kbase; if (rows>KC) rows=KC;
        if (t<rows) litem[t]=logs[bb*LL+kbase+t];
        __syncthreads();
        for (int u=t; u<rows*16; u+=256){
            int rrow=u>>4;
            ((float4*)E2c)[u]=((const float4*)g_E2)[(size_t)(bb*LL+kbase+rrow)*16+(u&15)];
            ((float4*)Sc)[u] =((const float4*)g_seqs_i)[(size_t)litem[rrow]*16+(u&15)];
        }
        __syncthreads();
        // phase B: scores
        for (int kl=kg; kl<rows; kl+=4){
            float acc=0.f;
            int kk=kbase+kl;
            if (q<LL && kk<=q){
                const float4* e2p=(const float4*)(E2c+kl*DD)+dh*8;
                #pragma unroll
                for (int j=0;j<8;j++){
                    float4 a=e1r[j], e=e2p[j], bv=br[j];
                    float u1,r1;
                    u1=1.f+fminf(a.x*e.x,1e30f); r1=fast_rcp(u1); acc=fmaf(bv.x,r1,acc);
                    u1=1.f+fminf(a.y*e.y,1e30f); r1=fast_rcp(u1); acc=fmaf(bv.y,r1,acc);
                    u1=1.f+fminf(a.z*e.z,1e30f); r1=fast_rcp(u1); acc=fmaf(bv.z,r1,acc);
                    u1=1.f+fminf(a.w*e.w,1e30f); r1=fast_rcp(u1); acc=fmaf(bv.w,r1,acc);
                }
            }
            acc += __shfl_xor_sync(0xffffffffu, acc, 4);
            if (dh==0 && q<LL && kk<=q) scc[qi*KC+kl]=acc;
        }
        __syncthreads();
        // phase C: accumulate final
        if (q<LL){
            int klmax=q-kbase+1; if (klmax>rows) klmax=rows; if (klmax<0) klmax=0;
            const float* sr=scc+qi*KC;
            for (int kl=0; kl<klmax; kl++){
                float sv=sr[kl];
                float4 s0=((float4*)(Sc+kl*DD))[dg*2];
                float4 s1=((float4*)(Sc+kl*DD))[dg*2+1];
                ac0.x=fmaf(sv,s0.x,ac0.x); ac0.y=fmaf(sv,s0.y,ac0.y);
                ac0.z=fmaf(sv,s0.z,ac0.z); ac0.w=fmaf(sv,s0.w,ac0.w);
                ac1.x=fmaf(sv,s1.x,ac1.x); ac1.y=fmaf(sv,s1.y,ac1.y);
                ac1.z=fmaf(sv,s1.z,ac1.z); ac1.w=fmaf(sv,s1.w,ac1.w);
            }
        }
        __syncthreads();
    }
    if (q<LL){
        float4* fp=((float4*)g_final)+(size_t)(bb*LL+q)*16;
        fp[dg*2]=ac0; fp[dg*2+1]=ac1;
    }
}

// ---------------- K4: FFN + UpDown + logits (register-tiled) ----------------
__global__ __launch_bounds__(256) void k4_ffn(const int* __restrict__ poss,
        const int* __restrict__ negs, const float* __restrict__ emb,
        const float* __restrict__ c1wg,const float* __restrict__ c1bg,
        const float* __restrict__ c2wg,const float* __restrict__ c2bg,
        const float* __restrict__ uwg,const float* __restrict__ ubg,
        const float* __restrict__ gwg,const float* __restrict__ gbg,
        const float* __restrict__ dwg,const float* __restrict__ dbg,
        float* __restrict__ out){
    extern __shared__ float sm[];
    float* c1w=sm;            // 4096
    float* c2w=sm+4096;       // 4096
    float* uw =sm+8192;       // 8192
    float* gw =sm+16384;      // 8192
    float* dw =sm+24576;      // 8192
    float* c1b=sm+32768; float* c2b=sm+32832;
    float* ub =sm+32896; float* gb =sm+33024; float* db=sm+33152;
    float* fin =sm+33216;     // 1024
    float* f1  =sm+34240;     // 1024
    float* fin2=sm+35264;     // 1024
    float* hb  =sm+36288;     // 2048
    float* fin3=sm+38336;     // 1024  (total 39360 floats)
    int t=threadIdx.x;
    for (int u=t;u<1024;u+=256){ ((float4*)c1w)[u]=((const float4*)c1wg)[u]; ((float4*)c2w)[u]=((const float4*)c2wg)[u]; }
    for (int u=t;u<2048;u+=256){ ((float4*)uw)[u]=((const float4*)uwg)[u]; ((float4*)gw)[u]=((const float4*)gwg)[u]; ((float4*)dw)[u]=((const float4*)dwg)[u]; }
    if (t<64){ c1b[t]=c1bg[t]; c2b[t]=c2bg[t]; db[t]=dbg[t]; }
    if (t<128){ ub[t]=ubg[t]; gb[t]=gbg[t]; }
    int p0=blockIdx.x*16;
    {
        int row=t>>4, col=t&15;
        ((float4*)fin)[t]=((float4*)g_final)[(size_t)(p0+row)*16+col];
    }
    __syncthreads();
    int tp=t>>4, dq=t&15;
    // stage 1: f1 = relu(fin@c1w + c1b)
    {
        float4 acc=((float4*)c1b)[dq];
        const float* xr=fin+tp*DD;
        #pragma unroll
        for (int k=0;k<DD;k++){
            float xv=xr[k]; float4 w=((float4*)c1w)[k*16+dq];
            acc.x=fmaf(xv,w.x,acc.x); acc.y=fmaf(xv,w.y,acc.y);
            acc.z=fmaf(xv,w.z,acc.z); acc.w=fmaf(xv,w.w,acc.w);
        }
        acc.x=fmaxf(acc.x,0.f); acc.y=fmaxf(acc.y,0.f); acc.z=fmaxf(acc.z,0.f); acc.w=fmaxf(acc.w,0.f);
        ((float4*)f1)[tp*16+dq]=acc;
    }
    __syncthreads();
    // stage 2: fin2 = fin + f1@c2w + c2b
    {
        float4 acc=((float4*)c2b)[dq];
        const float* xr=f1+tp*DD;
        #pragma unroll
        for (int k=0;k<DD;k++){
            float xv=xr[k]; float4 w=((float4*)c2w)[k*16+dq];
            acc.x=fmaf(xv,w.x,acc.x); acc.y=fmaf(xv,w.y,acc.y);
            acc.z=fmaf(xv,w.z,acc.z); acc.w=fmaf(xv,w.w,acc.w);
        }
        float4 fv=((float4*)fin)[tp*16+dq];
        acc.x+=fv.x; acc.y+=fv.y; acc.z+=fv.z; acc.w+=fv.w;
        ((float4*)fin2)[tp*16+dq]=acc;
    }
    __syncthreads();
    // stage 3: hb = relu(fin2@gw+gb) * (fin2@uw+ub), 128-wide
    {
        int rp=t>>5, dz=t&31;
        #pragma unroll
        for (int pass=0;pass<2;pass++){
            int row=rp+pass*8;
            float4 aU=((float4*)ub)[dz], aG=((float4*)gb)[dz];
            const float* x2=fin2+row*DD;
            #pragma unroll
            for (int k=0;k<DD;k++){
                float xv=x2[k];
                float4 wu=((float4*)uw)[k*32+dz], wg2=((float4*)gw)[k*32+dz];
                aU.x=fmaf(xv,wu.x,aU.x); aU.y=fmaf(xv,wu.y,aU.y); aU.z=fmaf(xv,wu.z,aU.z); aU.w=fmaf(xv,wu.w,aU.w);
                aG.x=fmaf(xv,wg2.x,aG.x); aG.y=fmaf(xv,wg2.y,aG.y); aG.z=fmaf(xv,wg2.z,aG.z); aG.w=fmaf(xv,wg2.w,aG.w);
            }
            float4 h;
            h.x=fmaxf(aG.x,0.f)*aU.x; h.y=fmaxf(aG.y,0.f)*aU.y;
            h.z=fmaxf(aG.z,0.f)*aU.z; h.w=fmaxf(aG.w,0.f)*aU.w;
            ((float4*)hb)[row*32+dz]=h;
        }
    }
    __syncthreads();
    // stage 4: fin3 = fin2 + relu(hb@dw + db)
    {
        float4 acc=((float4*)db)[dq];
        const float* hr=hb+tp*128;
        #pragma unroll
        for (int k=0;k<128;k++){
            float xv=hr[k]; float4 w=((float4*)dw)[k*16+dq];
            acc.x=fmaf(xv,w.x,acc.x); acc.y=fmaf(xv,w.y,acc.y);
            acc.z=fmaf(xv,w.z,acc.z); acc.w=fmaf(xv,w.w,acc.w);
        }
        float4 f2=((float4*)fin2)[tp*16+dq];
        float4 f3;
        f3.x=f2.x+fmaxf(acc.x,0.f); f3.y=f2.y+fmaxf(acc.y,0.f);
        f3.z=f2.z+fmaxf(acc.z,0.f); f3.w=f2.w+fmaxf(acc.w,0.f);
        ((float4*)fin3)[tp*16+dq]=f3;
    }
    __syncthreads();
    // logits
    {
        int w=t>>5, lane=t&31;
        int which=w&1, rb=w>>1;
        #pragma unroll
        for (int it=0; it<4; it++){
            int row=rb+it*4;
            int p=p0+row;
            int idx = which? negs[p] : poss[p];
            const float* er=emb+(size_t)idx*DD;
            const float* f3r=fin3+row*DD;
            float s=f3r[lane]*er[lane]+f3r[lane+32]*er[lane+32];
            #pragma unroll
            for (int o=16;o>0;o>>=1) s+=__shfl_xor_sync(0xffffffffu,s,o);
            if (lane==0) out[which*PP+p]=s;
        }
    }
}

// ---------------- host launcher ----------------
extern "C" void kernel_launch(void* const* d_in, const int* in_sizes, int n_in,
                              void* d_out, int out_size){
    const int*   logs = (const int*)  d_in[0];
    const int*   poss = (const int*)  d_in[1];
    const int*   negs = (const int*)  d_in[2];
    const float* adj  = (const float*)d_in[4];
    const float* emb  = (const float*)d_in[5];
    const float* pe   = (const float*)d_in[6];
    const float* Wi   = (const float*)d_in[7];
    const float* ai   = (const float*)d_in[8];
    const float* W1   = (const float*)d_in[9];
    const float* W2   = (const float*)d_in[10];
    const float* ba   = (const float*)d_in[11];
    const float* ccg  = (const float*)d_in[12];
    const float* cng  = (const float*)d_in[13];
    const float* c1w  = (const float*)d_in[14];
    const float* c1b  = (const float*)d_in[15];
    const float* c2w  = (const float*)d_in[16];
    const float* c2b  = (const float*)d_in[17];
    const float* uw   = (const float*)d_in[18];
    const float* ub   = (const float*)d_in[19];
    const float* gw   = (const float*)d_in[20];
    const float* gb   = (const float*)d_in[21];
    const float* dw   = (const float*)d_in[22];
    const float* db   = (const float*)d_in[23];
    float* out = (float*)d_out;

    cudaFuncSetAttribute(k2b_item, cudaFuncAttributeMaxDynamicSharedMemorySize, 81920);
    cudaFuncSetAttribute(k4_ffn,   cudaFuncAttributeMaxDynamicSharedMemorySize, 157440);

    k0_clear<<<24,256>>>();
    k0_mark<<<25,256>>>(logs);
    k1_hitem<<<(N1+15)/16,256>>>(emb, Wi, ai);
    k1b_hmean<<<16,256>>>();
    k1c_pproj<<<(LL+15)/16,256>>>(pe, W1, W2);
    k2a_gat<<<N1,256>>>(adj);
    k2b_item<<<(N1+15)/16,256,81920>>>(emb, ccg, cng, W1, W2);
    k2b_pos<<<PP/16,256>>>(logs);
    dim3 g3(7, BB);
    k3_attn<<<g3,256>>>(ba, logs);
    k4_ffn<<<PP/16,256,157440>>>(poss, negs, emb, c1w,c1b,c2w,c2b, uw,ub,gw,gb, dw,db, out);
}

// round 3
// speedup vs baseline: 1.6326x; 1.6326x over previous
#include <cuda_runtime.h>
#include <math.h>

#define N1 6001
#define DD 64
#define LL 200
#define BB 32
#define PP (BB*LL)      // 6400
#define QT 32
#define KC 64
#define RSTR 72         // padded smem row stride (floats); halves at +0 and +36
#define SCP 65
#define MAXNZ 1024

// ---------------- device scratch (zero-initialized at load) ----------------
__device__ __align__(16) float g_h[N1*DD];
__device__ float g_wh1[N1];
__device__ float g_wh2[N1];
__device__ int   g_flags[N1];
__device__ __align__(16) float g_gat_i[N1*DD];
__device__ __align__(16) float g_trans_i[N1*DD];
__device__ __align__(16) float g_seqs_i[N1*DD];
__device__ __align__(16) float g_A1[N1*DD];
__device__ __align__(16) float g_A2[N1*DD];
__device__ __align__(16) float g_P1[LL*DD];
__device__ __align__(16) float g_P2[LL*DD];
__device__ __align__(16) float g_final[PP*DD];

__device__ __forceinline__ float mufu_rcp(float u){
    float r;
    asm("rcp.approx.f32 %0, %1;" : "=f"(r) : "f"(u));
    return r;
}

// ============ K1 fused: hitem (bid<188) | pproj (188..194) | mark (195..207) ============
__global__ __launch_bounds__(512) void k1_fused(const float* __restrict__ emb,
        const float* __restrict__ Wi, const float* __restrict__ ai,
        const float* __restrict__ pe, const float* __restrict__ w1g,
        const float* __restrict__ w2g, const int* __restrict__ logs){
    __shared__ float sm[10368];
    int t = threadIdx.x;
    int bid = blockIdx.x;
    if (bid >= 195){
        int p = (bid-195)*512 + t;
        if (p < PP) g_flags[logs[p]] = 1;
        return;
    }
    if (bid < 188){
        float* Ws = sm; float* Xs = sm+4096; float* as_ = sm+6144;
        for (int u=t; u<1024; u+=512) ((float4*)Ws)[u] = ((const float4*)Wi)[u];
        if (t < 32) ((float4*)as_)[t] = ((const float4*)ai)[t];
        int r0 = bid*32;
        {
            int row=t>>4, col=t&15; int r=r0+row;
            float4 v = make_float4(0.f,0.f,0.f,0.f);
            if (r < N1) v = ((const float4*)(emb + r*DD))[col];
            ((float4*)Xs)[t] = v;
        }
        __syncthreads();
        int tp=t>>4, dq=t&15;
        float4 acc = make_float4(0.f,0.f,0.f,0.f);
        const float* xr = Xs + tp*DD;
        #pragma unroll
        for (int k=0;k<DD;k++){
            float xv = xr[k];
            float4 w = ((float4*)Ws)[k*16+dq];
            acc.x=fmaf(xv,w.x,acc.x); acc.y=fmaf(xv,w.y,acc.y);
            acc.z=fmaf(xv,w.z,acc.z); acc.w=fmaf(xv,w.w,acc.w);
        }
        int r = r0 + tp;
        if (r < N1) ((float4*)(g_h + r*DD))[dq] = acc;
        float4 a1=((float4*)as_)[dq], a2=((float4*)as_)[16+dq];
        float s1 = acc.x*a1.x+acc.y*a1.y+acc.z*a1.z+acc.w*a1.w;
        float s2 = acc.x*a2.x+acc.y*a2.y+acc.z*a2.z+acc.w*a2.w;
        #pragma unroll
        for (int o=8;o>0;o>>=1){
            s1 += __shfl_xor_sync(0xffffffffu, s1, o);
            s2 += __shfl_xor_sync(0xffffffffu, s2, o);
        }
        if (dq==0 && r<N1){ g_wh1[r]=s1; g_wh2[r]=s2; }
        return;
    }
    // pproj: P1 = pe@W1, P2 = pe@W2
    {
        float* W1s=sm; float* W2s=sm+4096; float* Xs=sm+8192;
        for (int u=t; u<1024; u+=512){
            ((float4*)W1s)[u]=((const float4*)w1g)[u];
            ((float4*)W2s)[u]=((const float4*)w2g)[u];
        }
        int l0 = (bid-188)*32;
        {
            int row=t>>4, col=t&15; int l=l0+row;
            float4 v = make_float4(0.f,0.f,0.f,0.f);
            if (l<LL) v = ((const float4*)(pe + l*DD))[col];
            ((float4*)Xs)[t]=v;
        }
        __syncthreads();
        int tp=t>>4, dq=t&15;
        float4 a1=make_float4(0.f,0.f,0.f,0.f), a2=a1;
        const float* xr = Xs + tp*DD;
        #pragma unroll
        for (int k=0;k<DD;k++){
            float xv=xr[k];
            float4 w1=((float4*)W1s)[k*16+dq], w2=((float4*)W2s)[k*16+dq];
            a1.x=fmaf(xv,w1.x,a1.x); a1.y=fmaf(xv,w1.y,a1.y); a1.z=fmaf(xv,w1.z,a1.z); a1.w=fmaf(xv,w1.w,a1.w);
            a2.x=fmaf(xv,w2.x,a2.x); a2.y=fmaf(xv,w2.y,a2.y); a2.z=fmaf(xv,w2.z,a2.z); a2.w=fmaf(xv,w2.w,a2.w);
        }
        int l=l0+tp;
        if (l<LL){ ((float4*)(g_P1+l*DD))[dq]=a1; ((float4*)(g_P2+l*DD))[dq]=a2; }
    }
}

// ============ K2a: sparse GAT per UNIQUE item (self-resets flag) ============
__global__ void k2a_gat(const float* __restrict__ adj){
    __shared__ int   s_idx[MAXNZ];
    __shared__ float s_val[MAXNZ];
    __shared__ float s_e[MAXNZ];
    __shared__ int wsum[8]; __shared__ int woff[8]; __shared__ int s_n;
    __shared__ float wred[8];
    __shared__ float pg[4][DD], pt[4][DD];
    int i = blockIdx.x;
    if (g_flags[i]==0) return;
    int t=threadIdx.x, lane=t&31, w=t>>5;
    const float* row = adj + (size_t)i*(size_t)N1;
    int c=0;
    for (int j=t;j<N1;j+=256) c += (row[j]>0.f)?1:0;
    int sc=c;
    #pragma unroll
    for (int o=1;o<32;o<<=1){ int v=__shfl_up_sync(0xffffffffu,sc,o); if(lane>=o) sc+=v; }
    if (lane==31) wsum[w]=sc;
    __syncthreads();
    if (t<8){
        int v=wsum[t]; int iv=v;
        #pragma unroll
        for (int o=1;o<8;o<<=1){ int u=__shfl_up_sync(0x000000ffu,iv,o); if(t>=o) iv+=u; }
        woff[t]=iv-v;
        if (t==7) s_n=iv;
    }
    __syncthreads();
    int off = woff[w] + (sc - c);
    for (int j=t;j<N1;j+=256){
        float a=row[j];
        if (a>0.f){ if(off<MAXNZ){ s_idx[off]=j; s_val[off]=a; } off++; }
    }
    __syncthreads();
    int n = s_n; if (n>MAXNZ) n=MAXNZ;
    int d=t&63, g4=t>>6;
    if (n==0){
        // exact fallback: softmax over all-(-9e15) row is uniform -> gat = mean(h)
        float s=0.f;
        for (int r=g4; r<N1; r+=4) s += g_h[r*DD+d];
        pg[g4][d]=s;
        __syncthreads();
        if (t<DD){
            float mm=(pg[0][t]+pg[1][t]+pg[2][t]+pg[3][t])*(1.f/(float)N1);
            g_gat_i[i*DD+t]=mm; g_trans_i[i*DD+t]=0.f;
        }
        if (t==0) g_flags[i]=0;
        return;
    }
    float wh1i = g_wh1[i];
    float m=-1e30f;
    for (int k=t;k<n;k+=256){
        float e = wh1i + g_wh2[s_idx[k]];
        e = (e>0.f)? e : 0.01f*e;
        s_e[k]=e;
        m = fmaxf(m,e);
    }
    #pragma unroll
    for (int o=16;o>0;o>>=1) m=fmaxf(m,__shfl_xor_sync(0xffffffffu,m,o));
    if (lane==0) wred[w]=m;
    __syncthreads();
    float M=wred[0];
    #pragma unroll
    for (int k=1;k<8;k++) M=fmaxf(M,wred[k]);
    __syncthreads();
    float ds=0.f;
    for (int k=t;k<n;k+=256){
        float wv=__expf(s_e[k]-M);
        s_e[k]=wv; ds+=wv;
    }
    #pragma unroll
    for (int o=16;o>0;o>>=1) ds += __shfl_xor_sync(0xffffffffu,ds,o);
    if (lane==0) wred[w]=ds;
    __syncthreads();
    float den=0.f;
    #pragma unroll
    for (int k=0;k<8;k++) den+=wred[k];
    float ga=0.f, ta=0.f;
    for (int k=g4;k<n;k+=4){
        float hv = g_h[s_idx[k]*DD+d];
        ga = fmaf(s_e[k],hv,ga);
        ta = fmaf(s_val[k],hv,ta);
    }
    pg[g4][d]=ga; pt[g4][d]=ta;
    __syncthreads();
    if (t<DD){
        float gg=(pg[0][t]+pg[1][t])+(pg[2][t]+pg[3][t]);
        float tt=(pt[0][t]+pt[1][t])+(pt[2][t]+pt[3][t]);
        float rden = mufu_rcp(den);
        g_gat_i[i*DD+t]=gg*rden; g_trans_i[i*DD+t]=tt;
    }
    if (t==0) g_flags[i]=0;
}

// ============ K2b_item: per-item coff/seqs + A1/A2 projections (512 thr, 32 rows) ============
__global__ __launch_bounds__(512) void k2b_item(const float* __restrict__ emb,
        const float* __restrict__ ccg, const float* __restrict__ cng,
        const float* __restrict__ w1g, const float* __restrict__ w2g){
    extern __shared__ float sm[];
    float* CC=sm; float* CN=sm+4096; float* W1s=sm+8192; float* W2s=sm+12288;
    float* Xg=sm+16384; float* Xt=Xg+2048; float* Xe=Xt+2048; float* X2=Xe+2048;
    int t=threadIdx.x;
    for (int u=t;u<1024;u+=512){
        ((float4*)CC)[u]=((const float4*)ccg)[u];
        ((float4*)CN)[u]=((const float4*)cng)[u];
        ((float4*)W1s)[u]=((const float4*)w1g)[u];
        ((float4*)W2s)[u]=((const float4*)w2g)[u];
    }
    int r0=blockIdx.x*32;
    {
        int row=t>>4, col=t&15; int r=r0+row;
        float4 g=make_float4(0.f,0.f,0.f,0.f), tv=g, e=g;
        if (r<N1){
            g =((float4*)g_gat_i)[r*16+col];
            tv=((float4*)g_trans_i)[r*16+col];
            e =((const float4*)(emb))[r*16+col];
        }
        ((float4*)Xg)[t]=g; ((float4*)Xt)[t]=tv; ((float4*)Xe)[t]=e;
    }
    __syncthreads();
    int tp=t>>4, dq=t&15;
    float4 x=make_float4(0.f,0.f,0.f,0.f);
    const float* gr=Xg+tp*DD; const float* trr=Xt+tp*DD;
    #pragma unroll
    for (int k=0;k<DD;k++){
        float gv=gr[k], tv=trr[k];
        float4 c1=((float4*)CC)[k*16+dq], c2=((float4*)CN)[k*16+dq];
        x.x=fmaf(gv,c1.x,fmaf(tv,c2.x,x.x));
        x.y=fmaf(gv,c1.y,fmaf(tv,c2.y,x.y));
        x.z=fmaf(gv,c1.z,fmaf(tv,c2.z,x.z));
        x.w=fmaf(gv,c1.w,fmaf(tv,c2.w,x.w));
    }
    float4 cf;
    cf.x=mufu_rcp(1.f+__expf(-x.x));
    cf.y=mufu_rcp(1.f+__expf(-x.y));
    cf.z=mufu_rcp(1.f+__expf(-x.z));
    cf.w=mufu_rcp(1.f+__expf(-x.w));
    float4 g4=((float4*)Xg)[tp*16+dq], t4=((float4*)Xt)[tp*16+dq], e4=((float4*)Xe)[tp*16+dq];
    float4 sv;
    sv.x=cf.x*g4.x+(1.f-cf.x)*t4.x+e4.x;
    sv.y=cf.y*g4.y+(1.f-cf.y)*t4.y+e4.y;
    sv.z=cf.z*g4.z+(1.f-cf.z)*t4.z+e4.z;
    sv.w=cf.w*g4.w+(1.f-cf.w)*t4.w+e4.w;
    ((float4*)X2)[tp*16+dq]=sv;
    int r=r0+tp;
    if (r<N1) ((float4*)g_seqs_i)[r*16+dq]=sv;
    __syncthreads();
    float4 a1=make_float4(0.f,0.f,0.f,0.f), a2=a1;
    const float* x2r=X2+tp*DD;
    #pragma unroll
    for (int k=0;k<DD;k++){
        float xv=x2r[k];
        float4 w1=((float4*)W1s)[k*16+dq], w2=((float4*)W2s)[k*16+dq];
        a1.x=fmaf(xv,w1.x,a1.x); a1.y=fmaf(xv,w1.y,a1.y); a1.z=fmaf(xv,w1.z,a1.z); a1.w=fmaf(xv,w1.w,a1.w);
        a2.x=fmaf(xv,w2.x,a2.x); a2.y=fmaf(xv,w2.y,a2.y); a2.z=fmaf(xv,w2.z,a2.z); a2.w=fmaf(xv,w2.w,a2.w);
    }
    if (r<N1){ ((float4*)g_A1)[r*16+dq]=a1; ((float4*)g_A2)[r*16+dq]=a2; }
}

// ============ K3: fused E-compute + score (MUFU rcp) + causal attend ============
__global__ __launch_bounds__(256,2) void k3_attn(const float* __restrict__ ba,
                                                 const int* __restrict__ logs){
    __shared__ float E2c[KC*RSTR];
    __shared__ float Sc[KC*RSTR];
    __shared__ float scc[QT*SCP];
    __shared__ int litem[KC];
    const int perm[7]={5,0,3,2,4,1,6};
    int t=threadIdx.x;
    int bb=blockIdx.y;
    int q0=perm[blockIdx.x]*QT;
    int qi=t>>3; int dh=(t>>2)&1; int kg=t&3; int dg=t&7;
    int q=q0+qi;
    bool valid = (q<LL);
    float4 e1r[8], br[8];
    {
        const float4* baf=(const float4*)ba;
        #pragma unroll
        for (int j=0;j<8;j++) br[j]=baf[dh*8+j];
        if (valid){
            int iq = logs[bb*LL+q];
            float mq = (iq!=0)? 1.f : 0.f;
            const float4* ap=((const float4*)g_A1)+(size_t)iq*16+dh*8;
            const float4* pp=((const float4*)g_P1)+(size_t)q*16+dh*8;
            #pragma unroll
            for (int j=0;j<8;j++){
                float4 a=ap[j], p=pp[j];
                e1r[j].x=__expf(-fmaf(mq,p.x,a.x));
                e1r[j].y=__expf(-fmaf(mq,p.y,a.y));
                e1r[j].z=__expf(-fmaf(mq,p.z,a.z));
                e1r[j].w=__expf(-fmaf(mq,p.w,a.w));
            }
        } else {
            #pragma unroll
            for (int j=0;j<8;j++) e1r[j]=make_float4(0.f,0.f,0.f,0.f);
        }
    }
    float4 ac0=make_float4(0.f,0.f,0.f,0.f), ac1=ac0;
    int kend=q0+QT; if (kend>LL) kend=LL;
    for (int kbase=0; kbase<kend; kbase+=KC){
        int rows=kend-kbase; if (rows>KC) rows=KC;
        if (t<rows) litem[t]=logs[bb*LL+kbase+t];
        __syncthreads();
        for (int u=t; u<rows*16; u+=256){
            int rrow=u>>4, col=u&15;
            int it=litem[rrow];
            int l=kbase+rrow;
            float m=(it!=0)? 1.f : 0.f;
            int off = rrow*RSTR + col*4 + ((col>=8)?4:0);
            float4 a=((const float4*)g_A2)[(size_t)it*16+col];
            float4 p=((const float4*)g_P2)[(size_t)l*16+col];
            float4 e;
            e.x=__expf(-fmaf(m,p.x,a.x));
            e.y=__expf(-fmaf(m,p.y,a.y));
            e.z=__expf(-fmaf(m,p.z,a.z));
            e.w=__expf(-fmaf(m,p.w,a.w));
            *(float4*)(E2c+off)=e;
            *(float4*)(Sc+off)=((const float4*)g_seqs_i)[(size_t)it*16+col];
        }
        __syncthreads();
        // phase B: scores via MUFU rcp
        for (int kl=kg; kl<rows; kl+=4){
            int kk=kbase+kl;
            bool act = valid && (kk<=q);
            float acc=0.f;
            if (act){
                const float4* e2p=(const float4*)(E2c + kl*RSTR) + dh*9;
                #pragma unroll
                for (int j=0;j<8;j++){
                    float4 a=e1r[j], e=e2p[j], bv=br[j];
                    acc=fmaf(bv.x, mufu_rcp(1.f+a.x*e.x), acc);
                    acc=fmaf(bv.y, mufu_rcp(1.f+a.y*e.y), acc);
                    acc=fmaf(bv.z, mufu_rcp(1.f+a.z*e.z), acc);
                    acc=fmaf(bv.w, mufu_rcp(1.f+a.w*e.w), acc);
                }
            }
            acc += __shfl_xor_sync(0xffffffffu, acc, 4);
            if (dh==0 && act) scc[qi*SCP+kl]=acc;
        }
        __syncthreads();
        // phase C: final accumulation
        if (valid){
            int klmax=q-kbase+1; if (klmax>rows) klmax=rows;
            const float* sr=scc+qi*SCP;
            int half = (dg>=4)? 4 : 0;
            for (int kl=0; kl<klmax; kl++){
                float sv=sr[kl];
                const float4* sp=(const float4*)(Sc + kl*RSTR + dg*8 + half);
                float4 s0=sp[0], s1=sp[1];
                ac0.x=fmaf(sv,s0.x,ac0.x); ac0.y=fmaf(sv,s0.y,ac0.y);
                ac0.z=fmaf(sv,s0.z,ac0.z); ac0.w=fmaf(sv,s0.w,ac0.w);
                ac1.x=fmaf(sv,s1.x,ac1.x); ac1.y=fmaf(sv,s1.y,ac1.y);
                ac1.z=fmaf(sv,s1.z,ac1.z); ac1.w=fmaf(sv,s1.w,ac1.w);
            }
        }
        __syncthreads();
    }
    if (valid){
        float4* fp=((float4*)g_final)+(size_t)(bb*LL+q)*16;
        fp[dg*2]=ac0; fp[dg*2+1]=ac1;
    }
}

// ============ K4: FFN + UpDown + logits (512 thr, 32 positions) ============
__global__ __launch_bounds__(512) void k4_ffn(const int* __restrict__ poss,
        const int* __restrict__ negs, const float* __restrict__ emb,
        const float* __restrict__ c1wg,const float* __restrict__ c1bg,
        const float* __restrict__ c2wg,const float* __restrict__ c2bg,
        const float* __restrict__ uwg,const float* __restrict__ ubg,
        const float* __restrict__ gwg,const float* __restrict__ gbg,
        const float* __restrict__ dwg,const float* __restrict__ dbg,
        float* __restrict__ out){
    extern __shared__ float sm[];
    float* c1w=sm;            // 4096
    float* c2w=sm+4096;       // 4096
    float* uw =sm+8192;       // 8192
    float* gw =sm+16384;      // 8192
    float* dw =sm+24576;      // 8192
    float* c1b=sm+32768; float* c2b=sm+32832;
    float* ub =sm+32896; float* gb =sm+33024; float* db=sm+33152;
    float* fin =sm+33216;     // 2048
    float* f1  =sm+35264;     // 2048
    float* fin2=sm+37312;     // 2048
    float* hb  =sm+39360;     // 4096
    float* fin3=sm+43456;     // 2048  (total 45504 floats)
    int t=threadIdx.x;
    for (int u=t;u<1024;u+=512){ ((float4*)c1w)[u]=((const float4*)c1wg)[u]; ((float4*)c2w)[u]=((const float4*)c2wg)[u]; }
    for (int u=t;u<2048;u+=512){ ((float4*)uw)[u]=((const float4*)uwg)[u]; ((float4*)gw)[u]=((const float4*)gwg)[u]; ((float4*)dw)[u]=((const float4*)dwg)[u]; }
    if (t<64){ c1b[t]=c1bg[t]; c2b[t]=c2bg[t]; db[t]=dbg[t]; }
    if (t<128){ ub[t]=ubg[t]; gb[t]=gbg[t]; }
    int p0=blockIdx.x*32;
    {
        int row=t>>4, col=t&15;
        ((float4*)fin)[t]=((float4*)g_final)[(size_t)(p0+row)*16+col];
    }
    __syncthreads();
    int tp=t>>4, dq=t&15;   // tp: 0..31 rows, dq: 16 float4 col groups
    // stage 1: f1 = relu(fin@c1w + c1b)
    {
        float4 acc=((float4*)c1b)[dq];
        const float* xr=fin+tp*DD;
        #pragma unroll
        for (int k=0;k<DD;k++){
            float xv=xr[k]; float4 w=((float4*)c1w)[k*16+dq];
            acc.x=fmaf(xv,w.x,acc.x); acc.y=fmaf(xv,w.y,acc.y);
            acc.z=fmaf(xv,w.z,acc.z); acc.w=fmaf(xv,w.w,acc.w);
        }
        acc.x=fmaxf(acc.x,0.f); acc.y=fmaxf(acc.y,0.f); acc.z=fmaxf(acc.z,0.f); acc.w=fmaxf(acc.w,0.f);
        ((float4*)f1)[tp*16+dq]=acc;
    }
    __syncthreads();
    // stage 2: fin2 = fin + f1@c2w + c2b
    {
        float4 acc=((float4*)c2b)[dq];
        const float* xr=f1+tp*DD;
        #pragma unroll
        for (int k=0;k<DD;k++){
            float xv=xr[k]; float4 w=((float4*)c2w)[k*16+dq];
            acc.x=fmaf(xv,w.x,acc.x); acc.y=fmaf(xv,w.y,acc.y);
            acc.z=fmaf(xv,w.z,acc.z); acc.w=fmaf(xv,w.w,acc.w);
        }
        float4 fv=((float4*)fin)[tp*16+dq];
        acc.x+=fv.x; acc.y+=fv.y; acc.z+=fv.z; acc.w+=fv.w;
        ((float4*)fin2)[tp*16+dq]=acc;
    }
    __syncthreads();
    // stage 3: hb = relu(fin2@gw+gb) * (fin2@uw+ub), 128-wide: each thread 2 float4 cols
    {
        float4 aU0=((float4*)ub)[dq],    aG0=((float4*)gb)[dq];
        float4 aU1=((float4*)ub)[dq+16], aG1=((float4*)gb)[dq+16];
        const float* x2=fin2+tp*DD;
        #pragma unroll
        for (int k=0;k<DD;k++){
            float xv=x2[k];
            float4 wu0=((float4*)uw)[k*32+dq],    wg0=((float4*)gw)[k*32+dq];
            float4 wu1=((float4*)uw)[k*32+dq+16], wg1=((float4*)gw)[k*32+dq+16];
            aU0.x=fmaf(xv,wu0.x,aU0.x); aU0.y=fmaf(xv,wu0.y,aU0.y); aU0.z=fmaf(xv,wu0.z,aU0.z); aU0.w=fmaf(xv,wu0.w,aU0.w);
            aG0.x=fmaf(xv,wg0.x,aG0.x); aG0.y=fmaf(xv,wg0.y,aG0.y); aG0.z=fmaf(xv,wg0.z,aG0.z); aG0.w=fmaf(xv,wg0.w,aG0.w);
            aU1.x=fmaf(xv,wu1.x,aU1.x); aU1.y=fmaf(xv,wu1.y,aU1.y); aU1.z=fmaf(xv,wu1.z,aU1.z); aU1.w=fmaf(xv,wu1.w,aU1.w);
            aG1.x=fmaf(xv,wg1.x,aG1.x); aG1.y=fmaf(xv,wg1.y,aG1.y); aG1.z=fmaf(xv,wg1.z,aG1.z); aG1.w=fmaf(xv,wg1.w,aG1.w);
        }
        float4 h0, h1;
        h0.x=fmaxf(aG0.x,0.f)*aU0.x; h0.y=fmaxf(aG0.y,0.f)*aU0.y;
        h0.z=fmaxf(aG0.z,0.f)*aU0.z; h0.w=fmaxf(aG0.w,0.f)*aU0.w;
        h1.x=fmaxf(aG1.x,0.f)*aU1.x; h1.y=fmaxf(aG1.y,0.f)*aU1.y;
        h1.z=fmaxf(aG1.z,0.f)*aU1.z; h1.w=fmaxf(aG1.w,0.f)*aU1.w;
        ((float4*)hb)[tp*32+dq]=h0;
        ((float4*)hb)[tp*32+dq+16]=h1;
    }
    __syncthreads();
    // stage 4: fin3 = fin2 + relu(hb@dw + db)
    {
        float4 acc=((float4*)db)[dq];
        const float* hr=hb+tp*128;
        #pragma unroll
        for (int k=0;k<128;k++){
            float xv=hr[k]; float4 w=((float4*)dw)[k*16+dq];
            acc.x=fmaf(xv,w.x,acc.x); acc.y=fmaf(xv,w.y,acc.y);
            acc.z=fmaf(xv,w.z,acc.z); acc.w=fmaf(xv,w.w,acc.w);
        }
        float4 f2=((float4*)fin2)[tp*16+dq];
        float4 f3;
        f3.x=f2.x+fmaxf(acc.x,0.f); f3.y=f2.y+fmaxf(acc.y,0.f);
        f3.z=f2.z+fmaxf(acc.z,0.f); f3.w=f2.w+fmaxf(acc.w,0.f);
        ((float4*)fin3)[tp*16+dq]=f3;
    }
    __syncthreads();
    // logits: 16 warps x 4 iterations cover 32 pos x {pos,neg}
    {
        int w=t>>5, lane=t&31;
        int which=w&1, rb=w>>1;
        #pragma unroll
        for (int it=0; it<4; it++){
            int row=rb+it*8;
            int p=p0+row;
            int idx = which? negs[p] : poss[p];
            const float* er=emb+(size_t)idx*DD;
            const float* f3r=fin3+row*DD;
            float s=f3r[lane]*er[lane]+f3r[lane+32]*er[lane+32];
            #pragma unroll
            for (int o=16;o>0;o>>=1) s+=__shfl_xor_sync(0xffffffffu,s,o);
            if (lane==0) out[which*PP+p]=s;
        }
    }
}

// ---------------- host launcher ----------------
extern "C" void kernel_launch(void* const* d_in, const int* in_sizes, int n_in,
                              void* d_out, int out_size){
    const int*   logs = (const int*)  d_in[0];
    const int*   poss = (const int*)  d_in[1];
    const int*   negs = (const int*)  d_in[2];
    const float* adj  = (const float*)d_in[4];
    const float* emb  = (const float*)d_in[5];
    const float* pe   = (const float*)d_in[6];
    const float* Wi   = (const float*)d_in[7];
    const float* ai   = (const float*)d_in[8];
    const float* W1   = (const float*)d_in[9];
    const float* W2   = (const float*)d_in[10];
    const float* ba   = (const float*)d_in[11];
    const float* ccg  = (const float*)d_in[12];
    const float* cng  = (const float*)d_in[13];
    const float* c1w  = (const float*)d_in[14];
    const float* c1b  = (const float*)d_in[15];
    const float* c2w  = (const float*)d_in[16];
    const float* c2b  = (const float*)d_in[17];
    const float* uw   = (const float*)d_in[18];
    const float* ub   = (const float*)d_in[19];
    const float* gw   = (const float*)d_in[20];
    const float* gb   = (const float*)d_in[21];
    const float* dw   = (const float*)d_in[22];
    const float* db   = (const float*)d_in[23];
    float* out = (float*)d_out;

    cudaFuncSetAttribute(k2b_item, cudaFuncAttributeMaxDynamicSharedMemorySize, 98304);
    cudaFuncSetAttribute(k4_ffn,   cudaFuncAttributeMaxDynamicSharedMemorySize, 182016);

    k1_fused<<<208,512>>>(emb, Wi, ai, pe, W1, W2, logs);
    k2a_gat<<<N1,256>>>(adj);
    k2b_item<<<188,512,98304>>>(emb, ccg, cng, W1, W2);
    dim3 g3(7, BB);
    k3_attn<<<g3,256>>>(ba, logs);
    k4_ffn<<<200,512,182016>>>(poss, negs, emb, c1w,c1b,c2w,c2b, uw,ub,gw,gb, dw,db, out);
}

// round 4
// speedup vs baseline: 1.7358x; 1.0633x over previous
#include <cuda_runtime.h>
#include <math.h>

#define N1 6001
#define DD 64
#define LL 200
#define BB 32
#define PP (BB*LL)      // 6400
#define MAXNZ 1024
#define RS 68           // k3 smem row stride (floats): 68 mod 32 = 4 -> conflict-free group layout

// ---------------- device scratch (zero-initialized at load) ----------------
__device__ __align__(16) float g_h[N1*DD];
__device__ float g_wh1[N1];
__device__ float g_wh2[N1];
__device__ int   g_flags[N1];
__device__ __align__(16) float g_gat_i[N1*DD];
__device__ __align__(16) float g_trans_i[N1*DD];
__device__ __align__(16) float g_seqs_i[N1*DD];
__device__ __align__(16) float g_A1[N1*DD];
__device__ __align__(16) float g_A2[N1*DD];
__device__ __align__(16) float g_P1[LL*DD];
__device__ __align__(16) float g_P2[LL*DD];
__device__ __align__(16) float g_final[PP*DD];

__device__ __forceinline__ float mufu_rcp(float u){
    float r;
    asm("rcp.approx.f32 %0, %1;" : "=f"(r) : "f"(u));
    return r;
}

// ============ K1 fused: hitem (bid<188) | pproj (188..194) | mark (195..207) ============
__global__ __launch_bounds__(512) void k1_fused(const float* __restrict__ emb,
        const float* __restrict__ Wi, const float* __restrict__ ai,
        const float* __restrict__ pe, const float* __restrict__ w1g,
        const float* __restrict__ w2g, const int* __restrict__ logs){
    __shared__ float sm[10368];
    int t = threadIdx.x;
    int bid = blockIdx.x;
    if (bid >= 195){
        int p = (bid-195)*512 + t;
        if (p < PP) g_flags[logs[p]] = 1;
        return;
    }
    if (bid < 188){
        float* Ws = sm; float* Xs = sm+4096; float* as_ = sm+6144;
        for (int u=t; u<1024; u+=512) ((float4*)Ws)[u] = ((const float4*)Wi)[u];
        if (t < 32) ((float4*)as_)[t] = ((const float4*)ai)[t];
        int r0 = bid*32;
        {
            int row=t>>4, col=t&15; int r=r0+row;
            float4 v = make_float4(0.f,0.f,0.f,0.f);
            if (r < N1) v = ((const float4*)(emb + r*DD))[col];
            ((float4*)Xs)[t] = v;
        }
        __syncthreads();
        int tp=t>>4, dq=t&15;
        float4 acc = make_float4(0.f,0.f,0.f,0.f);
        const float* xr = Xs + tp*DD;
        #pragma unroll
        for (int k=0;k<DD;k++){
            float xv = xr[k];
            float4 w = ((float4*)Ws)[k*16+dq];
            acc.x=fmaf(xv,w.x,acc.x); acc.y=fmaf(xv,w.y,acc.y);
            acc.z=fmaf(xv,w.z,acc.z); acc.w=fmaf(xv,w.w,acc.w);
        }
        int r = r0 + tp;
        if (r < N1) ((float4*)(g_h + r*DD))[dq] = acc;
        float4 a1=((float4*)as_)[dq], a2=((float4*)as_)[16+dq];
        float s1 = acc.x*a1.x+acc.y*a1.y+acc.z*a1.z+acc.w*a1.w;
        float s2 = acc.x*a2.x+acc.y*a2.y+acc.z*a2.z+acc.w*a2.w;
        #pragma unroll
        for (int o=8;o>0;o>>=1){
            s1 += __shfl_xor_sync(0xffffffffu, s1, o);
            s2 += __shfl_xor_sync(0xffffffffu, s2, o);
        }
        if (dq==0 && r<N1){ g_wh1[r]=s1; g_wh2[r]=s2; }
        return;
    }
    // pproj: P1 = pe@W1, P2 = pe@W2
    {
        float* W1s=sm; float* W2s=sm+4096; float* Xs=sm+8192;
        for (int u=t; u<1024; u+=512){
            ((float4*)W1s)[u]=((const float4*)w1g)[u];
            ((float4*)W2s)[u]=((const float4*)w2g)[u];
        }
        int l0 = (bid-188)*32;
        {
            int row=t>>4, col=t&15; int l=l0+row;
            float4 v = make_float4(0.f,0.f,0.f,0.f);
            if (l<LL) v = ((const float4*)(pe + l*DD))[col];
            ((float4*)Xs)[t]=v;
        }
        __syncthreads();
        int tp=t>>4, dq=t&15;
        float4 a1=make_float4(0.f,0.f,0.f,0.f), a2=a1;
        const float* xr = Xs + tp*DD;
        #pragma unroll
        for (int k=0;k<DD;k++){
            float xv=xr[k];
            float4 w1=((float4*)W1s)[k*16+dq], w2=((float4*)W2s)[k*16+dq];
            a1.x=fmaf(xv,w1.x,a1.x); a1.y=fmaf(xv,w1.y,a1.y); a1.z=fmaf(xv,w1.z,a1.z); a1.w=fmaf(xv,w1.w,a1.w);
            a2.x=fmaf(xv,w2.x,a2.x); a2.y=fmaf(xv,w2.y,a2.y); a2.z=fmaf(xv,w2.z,a2.z); a2.w=fmaf(xv,w2.w,a2.w);
        }
        int l=l0+tp;
        if (l<LL){ ((float4*)(g_P1+l*DD))[dq]=a1; ((float4*)(g_P2+l*DD))[dq]=a2; }
    }
}

// ============ K2a: sparse GAT per UNIQUE item (self-resets flag) ============
__global__ void k2a_gat(const float* __restrict__ adj){
    __shared__ int   s_idx[MAXNZ];
    __shared__ float s_val[MAXNZ];
    __shared__ float s_e[MAXNZ];
    __shared__ int wsum[8]; __shared__ int woff[8]; __shared__ int s_n;
    __shared__ float wred[8];
    __shared__ float pg[4][DD], pt[4][DD];
    int i = blockIdx.x;
    if (g_flags[i]==0) return;
    int t=threadIdx.x, lane=t&31, w=t>>5;
    const float* row = adj + (size_t)i*(size_t)N1;
    int c=0;
    for (int j=t;j<N1;j+=256) c += (row[j]>0.f)?1:0;
    int sc=c;
    #pragma unroll
    for (int o=1;o<32;o<<=1){ int v=__shfl_up_sync(0xffffffffu,sc,o); if(lane>=o) sc+=v; }
    if (lane==31) wsum[w]=sc;
    __syncthreads();
    if (t<8){
        int v=wsum[t]; int iv=v;
        #pragma unroll
        for (int o=1;o<8;o<<=1){ int u=__shfl_up_sync(0x000000ffu,iv,o); if(t>=o) iv+=u; }
        woff[t]=iv-v;
        if (t==7) s_n=iv;
    }
    __syncthreads();
    int off = woff[w] + (sc - c);
    for (int j=t;j<N1;j+=256){
        float a=row[j];
        if (a>0.f){ if(off<MAXNZ){ s_idx[off]=j; s_val[off]=a; } off++; }
    }
    __syncthreads();
    int n = s_n; if (n>MAXNZ) n=MAXNZ;
    int d=t&63, g4=t>>6;
    if (n==0){
        float s=0.f;
        for (int r=g4; r<N1; r+=4) s += g_h[r*DD+d];
        pg[g4][d]=s;
        __syncthreads();
        if (t<DD){
            float mm=(pg[0][t]+pg[1][t]+pg[2][t]+pg[3][t])*(1.f/(float)N1);
            g_gat_i[i*DD+t]=mm; g_trans_i[i*DD+t]=0.f;
        }
        if (t==0) g_flags[i]=0;
        return;
    }
    float wh1i = g_wh1[i];
    float m=-1e30f;
    for (int k=t;k<n;k+=256){
        float e = wh1i + g_wh2[s_idx[k]];
        e = (e>0.f)? e : 0.01f*e;
        s_e[k]=e;
        m = fmaxf(m,e);
    }
    #pragma unroll
    for (int o=16;o>0;o>>=1) m=fmaxf(m,__shfl_xor_sync(0xffffffffu,m,o));
    if (lane==0) wred[w]=m;
    __syncthreads();
    float M=wred[0];
    #pragma unroll
    for (int k=1;k<8;k++) M=fmaxf(M,wred[k]);
    __syncthreads();
    float ds=0.f;
    for (int k=t;k<n;k+=256){
        float wv=__expf(s_e[k]-M);
        s_e[k]=wv; ds+=wv;
    }
    #pragma unroll
    for (int o=16;o>0;o>>=1) ds += __shfl_xor_sync(0xffffffffu,ds,o);
    if (lane==0) wred[w]=ds;
    __syncthreads();
    float den=0.f;
    #pragma unroll
    for (int k=0;k<8;k++) den+=wred[k];
    float ga=0.f, ta=0.f;
    for (int k=g4;k<n;k+=4){
        float hv = g_h[s_idx[k]*DD+d];
        ga = fmaf(s_e[k],hv,ga);
        ta = fmaf(s_val[k],hv,ta);
    }
    pg[g4][d]=ga; pt[g4][d]=ta;
    __syncthreads();
    if (t<DD){
        float gg=(pg[0][t]+pg[1][t])+(pg[2][t]+pg[3][t]);
        float tt=(pt[0][t]+pt[1][t])+(pt[2][t]+pt[3][t]);
        float rden = mufu_rcp(den);
        g_gat_i[i*DD+t]=gg*rden; g_trans_i[i*DD+t]=tt;
    }
    if (t==0) g_flags[i]=0;
}

// ============ K2b_item: per-item coff/seqs + A1/A2 projections ============
__global__ __launch_bounds__(512) void k2b_item(const float* __restrict__ emb,
        const float* __restrict__ ccg, const float* __restrict__ cng,
        const float* __restrict__ w1g, const float* __restrict__ w2g){
    extern __shared__ float sm[];
    float* CC=sm; float* CN=sm+4096; float* W1s=sm+8192; float* W2s=sm+12288;
    float* Xg=sm+16384; float* Xt=Xg+2048; float* Xe=Xt+2048; float* X2=Xe+2048;
    int t=threadIdx.x;
    for (int u=t;u<1024;u+=512){
        ((float4*)CC)[u]=((const float4*)ccg)[u];
        ((float4*)CN)[u]=((const float4*)cng)[u];
        ((float4*)W1s)[u]=((const float4*)w1g)[u];
        ((float4*)W2s)[u]=((const float4*)w2g)[u];
    }
    int r0=blockIdx.x*32;
    {
        int row=t>>4, col=t&15; int r=r0+row;
        float4 g=make_float4(0.f,0.f,0.f,0.f), tv=g, e=g;
        if (r<N1){
            g =((float4*)g_gat_i)[r*16+col];
            tv=((float4*)g_trans_i)[r*16+col];
            e =((const float4*)(emb))[r*16+col];
        }
        ((float4*)Xg)[t]=g; ((float4*)Xt)[t]=tv; ((float4*)Xe)[t]=e;
    }
    __syncthreads();
    int tp=t>>4, dq=t&15;
    float4 x=make_float4(0.f,0.f,0.f,0.f);
    const float* gr=Xg+tp*DD; const float* trr=Xt+tp*DD;
    #pragma unroll
    for (int k=0;k<DD;k++){
        float gv=gr[k], tv=trr[k];
        float4 c1=((float4*)CC)[k*16+dq], c2=((float4*)CN)[k*16+dq];
        x.x=fmaf(gv,c1.x,fmaf(tv,c2.x,x.x));
        x.y=fmaf(gv,c1.y,fmaf(tv,c2.y,x.y));
        x.z=fmaf(gv,c1.z,fmaf(tv,c2.z,x.z));
        x.w=fmaf(gv,c1.w,fmaf(tv,c2.w,x.w));
    }
    float4 cf;
    cf.x=mufu_rcp(1.f+__expf(-x.x));
    cf.y=mufu_rcp(1.f+__expf(-x.y));
    cf.z=mufu_rcp(1.f+__expf(-x.z));
    cf.w=mufu_rcp(1.f+__expf(-x.w));
    float4 g4=((float4*)Xg)[tp*16+dq], t4=((float4*)Xt)[tp*16+dq], e4=((float4*)Xe)[tp*16+dq];
    float4 sv;
    sv.x=cf.x*g4.x+(1.f-cf.x)*t4.x+e4.x;
    sv.y=cf.y*g4.y+(1.f-cf.y)*t4.y+e4.y;
    sv.z=cf.z*g4.z+(1.f-cf.z)*t4.z+e4.z;
    sv.w=cf.w*g4.w+(1.f-cf.w)*t4.w+e4.w;
    ((float4*)X2)[tp*16+dq]=sv;
    int r=r0+tp;
    if (r<N1) ((float4*)g_seqs_i)[r*16+dq]=sv;
    __syncthreads();
    float4 a1=make_float4(0.f,0.f,0.f,0.f), a2=a1;
    const float* x2r=X2+tp*DD;
    #pragma unroll
    for (int k=0;k<DD;k++){
        float xv=x2r[k];
        float4 w1=((float4*)W1s)[k*16+dq], w2=((float4*)W2s)[k*16+dq];
        a1.x=fmaf(xv,w1.x,a1.x); a1.y=fmaf(xv,w1.y,a1.y); a1.z=fmaf(xv,w1.z,a1.z); a1.w=fmaf(xv,w1.w,a1.w);
        a2.x=fmaf(xv,w2.x,a2.x); a2.y=fmaf(xv,w2.y,a2.y); a2.z=fmaf(xv,w2.z,a2.z); a2.w=fmaf(xv,w2.w,a2.w);
    }
    if (r<N1){ ((float4*)g_A1)[r*16+dq]=a1; ((float4*)g_A2)[r*16+dq]=a2; }
}

// ============ K3: mirrored-pair causal attention, full-d per thread ============
// Block = (pair p, batch bb). Tiles (p, 12-p) of 16 q-rows each -> balanced work.
__global__ __launch_bounds__(256,4) void k3_attn(const float* __restrict__ ba,
                                                 const int* __restrict__ logs){
    __shared__ float E1s[32*RS];
    __shared__ float E2c[32*RS];
    __shared__ float Sc[32*RS];
    __shared__ float bs[64];
    __shared__ float scc[32*36];
    __shared__ int litem[32];
    int t=threadIdx.x;
    int bb=blockIdx.y;
    int p=blockIdx.x;
    int tA=p, tB=12-p;
    bool self = (tA==tB);
    int qA0=tA*16, qB0=tB*16;
    int kendMax = (tB+1)*16; if (kendMax>LL) kendMax=LL;

    if (t<16) ((float4*)bs)[t]=((const float4*)ba)[t];
    // load E1 for both q-tiles (rows 0..15 = tileA, 16..31 = tileB)
    for (int u=t; u<512; u+=256){
        int r=u>>4, col=u&15;
        int q = (r<16)? (qA0+r) : (qB0+r-16);
        bool ok = (q<LL) && !(self && r>=16);
        float4 e = make_float4(0.f,0.f,0.f,0.f);
        if (ok){
            int iq = logs[bb*LL+q];
            float m = (iq!=0)? 1.f : 0.f;
            float4 a=((const float4*)g_A1)[(size_t)iq*16+col];
            float4 pp=((const float4*)g_P1)[(size_t)q*16+col];
            e.x=__expf(-fmaf(m,pp.x,a.x));
            e.y=__expf(-fmaf(m,pp.y,a.y));
            e.z=__expf(-fmaf(m,pp.z,a.z));
            e.w=__expf(-fmaf(m,pp.w,a.w));
        }
        *(float4*)(E1s + r*RS + col*4) = e;
    }
    __syncthreads();

    int qi=t>>3, klg=t&7;          // phase B mapping
    int dg=t&7;                    // phase C mapping (same qi)
    int q = (qi<16)? (qA0+qi) : (qB0+qi-16);
    bool qvalid = (q<LL) && !(self && qi>=16);
    float4 ac0=make_float4(0.f,0.f,0.f,0.f), ac1=ac0;

    for (int kbase=0; kbase<kendMax; kbase+=32){
        int rows = kendMax-kbase; if (rows>32) rows=32;
        if (t<rows) litem[t]=logs[bb*LL+kbase+t];
        __syncthreads();
        for (int u=t; u<rows*16; u+=256){
            int r=u>>4, col=u&15;
            int it=litem[r];
            int l=kbase+r;
            float m=(it!=0)? 1.f : 0.f;
            float4 a=((const float4*)g_A2)[(size_t)it*16+col];
            float4 pp=((const float4*)g_P2)[(size_t)l*16+col];
            float4 e;
            e.x=__expf(-fmaf(m,pp.x,a.x));
            e.y=__expf(-fmaf(m,pp.y,a.y));
            e.z=__expf(-fmaf(m,pp.z,a.z));
            e.w=__expf(-fmaf(m,pp.w,a.w));
            *(float4*)(E2c + r*RS + col*4) = e;
            *(float4*)(Sc  + r*RS + col*4) = ((const float4*)g_seqs_i)[(size_t)it*16+col];
        }
        __syncthreads();
        // phase B: one thread per (q, k) pair, full 64-d
        if (qvalid && kbase<=q){
            const float* e1p = E1s + qi*RS;
            for (int kl=klg; kl<rows; kl+=8){
                int kk=kbase+kl;
                if (kk<=q){
                    const float* e2p = E2c + kl*RS;
                    float acc=0.f;
                    #pragma unroll
                    for (int j=0;j<16;j++){
                        float4 a=*(const float4*)(e1p+j*4);
                        float4 e=*(const float4*)(e2p+j*4);
                        float4 b=*(const float4*)(bs+j*4);
                        acc=fmaf(b.x, mufu_rcp(fmaf(a.x,e.x,1.f)), acc);
                        acc=fmaf(b.y, mufu_rcp(fmaf(a.y,e.y,1.f)), acc);
                        acc=fmaf(b.z, mufu_rcp(fmaf(a.z,e.z,1.f)), acc);
                        acc=fmaf(b.w, mufu_rcp(fmaf(a.w,e.w,1.f)), acc);
                    }
                    scc[qi*36+kl]=acc;
                }
            }
        }
        __syncthreads();
        // phase C: final[q,d] += sum_k score * seqs[k,d]
        if (qvalid && kbase<=q){
            int klmax=q-kbase+1; if (klmax>rows) klmax=rows;
            const float* sr=scc+qi*36;
            for (int kl=0; kl<klmax; kl++){
                float sv=sr[kl];
                float4 s0=*(const float4*)(Sc + kl*RS + dg*4);
                float4 s1=*(const float4*)(Sc + kl*RS + dg*4 + 32);
                ac0.x=fmaf(sv,s0.x,ac0.x); ac0.y=fmaf(sv,s0.y,ac0.y);
                ac0.z=fmaf(sv,s0.z,ac0.z); ac0.w=fmaf(sv,s0.w,ac0.w);
                ac1.x=fmaf(sv,s1.x,ac1.x); ac1.y=fmaf(sv,s1.y,ac1.y);
                ac1.z=fmaf(sv,s1.z,ac1.z); ac1.w=fmaf(sv,s1.w,ac1.w);
            }
        }
        __syncthreads();
    }
    if (qvalid){
        float4* fp=((float4*)g_final)+(size_t)(bb*LL+q)*16;
        fp[dg]=ac0; fp[dg+8]=ac1;
    }
}

// ============ K4: FFN + UpDown + logits (512 thr, 32 positions) ============
__global__ __launch_bounds__(512) void k4_ffn(const int* __restrict__ poss,
        const int* __restrict__ negs, const float* __restrict__ emb,
        const float* __restrict__ c1wg,const float* __restrict__ c1bg,
        const float* __restrict__ c2wg,const float* __restrict__ c2bg,
        const float* __restrict__ uwg,const float* __restrict__ ubg,
        const float* __restrict__ gwg,const float* __restrict__ gbg,
        const float* __restrict__ dwg,const float* __restrict__ dbg,
        float* __restrict__ out){
    extern __shared__ float sm[];
    float* c1w=sm;            // 4096
    float* c2w=sm+4096;       // 4096
    float* uw =sm+8192;       // 8192
    float* gw =sm+16384;      // 8192
    float* dw =sm+24576;      // 8192
    float* c1b=sm+32768; float* c2b=sm+32832;
    float* ub =sm+32896; float* gb =sm+33024; float* db=sm+33152;
    float* fin =sm+33216;     // 2048
    float* f1  =sm+35264;     // 2048
    float* fin2=sm+37312;     // 2048
    float* hb  =sm+39360;     // 4096
    float* fin3=sm+43456;     // 2048
    int t=threadIdx.x;
    for (int u=t;u<1024;u+=512){ ((float4*)c1w)[u]=((const float4*)c1wg)[u]; ((float4*)c2w)[u]=((const float4*)c2wg)[u]; }
    for (int u=t;u<2048;u+=512){ ((float4*)uw)[u]=((const float4*)uwg)[u]; ((float4*)gw)[u]=((const float4*)gwg)[u]; ((float4*)dw)[u]=((const float4*)dwg)[u]; }
    if (t<64){ c1b[t]=c1bg[t]; c2b[t]=c2bg[t]; db[t]=dbg[t]; }
    if (t<128){ ub[t]=ubg[t]; gb[t]=gbg[t]; }
    int p0=blockIdx.x*32;
    {
        int row=t>>4, col=t&15;
        ((float4*)fin)[t]=((float4*)g_final)[(size_t)(p0+row)*16+col];
    }
    __syncthreads();
    int tp=t>>4, dq=t&15;
    {
        float4 acc=((float4*)c1b)[dq];
        const float* xr=fin+tp*DD;
        #pragma unroll
        for (int k=0;k<DD;k++){
            float xv=xr[k]; float4 w=((float4*)c1w)[k*16+dq];
            acc.x=fmaf(xv,w.x,acc.x); acc.y=fmaf(xv,w.y,acc.y);
            acc.z=fmaf(xv,w.z,acc.z); acc.w=fmaf(xv,w.w,acc.w);
        }
        acc.x=fmaxf(acc.x,0.f); acc.y=fmaxf(acc.y,0.f); acc.z=fmaxf(acc.z,0.f); acc.w=fmaxf(acc.w,0.f);
        ((float4*)f1)[tp*16+dq]=acc;
    }
    __syncthreads();
    {
        float4 acc=((float4*)c2b)[dq];
        const float* xr=f1+tp*DD;
        #pragma unroll
        for (int k=0;k<DD;k++){
            float xv=xr[k]; float4 w=((float4*)c2w)[k*16+dq];
            acc.x=fmaf(xv,w.x,acc.x); acc.y=fmaf(xv,w.y,acc.y);
            acc.z=fmaf(xv,w.z,acc.z); acc.w=fmaf(xv,w.w,acc.w);
        }
        float4 fv=((float4*)fin)[tp*16+dq];
        acc.x+=fv.x; acc.y+=fv.y; acc.z+=fv.z; acc.w+=fv.w;
        ((float4*)fin2)[tp*16+dq]=acc;
    }
    __syncthreads();
    {
        float4 aU0=((float4*)ub)[dq],    aG0=((float4*)gb)[dq];
        float4 aU1=((float4*)ub)[dq+16], aG1=((float4*)gb)[dq+16];
        const float* x2=fin2+tp*DD;
        #pragma unroll
        for (int k=0;k<DD;k++){
            float xv=x2[k];
            float4 wu0=((float4*)uw)[k*32+dq],    wg0=((float4*)gw)[k*32+dq];
            float4 wu1=((float4*)uw)[k*32+dq+16], wg1=((float4*)gw)[k*32+dq+16];
            aU0.x=fmaf(xv,wu0.x,aU0.x); aU0.y=fmaf(xv,wu0.y,aU0.y); aU0.z=fmaf(xv,wu0.z,aU0.z); aU0.w=fmaf(xv,wu0.w,aU0.w);
            aG0.x=fmaf(xv,wg0.x,aG0.x); aG0.y=fmaf(xv,wg0.y,aG0.y); aG0.z=fmaf(xv,wg0.z,aG0.z); aG0.w=fmaf(xv,wg0.w,aG0.w);
            aU1.x=fmaf(xv,wu1.x,aU1.x); aU1.y=fmaf(xv,wu1.y,aU1.y); aU1.z=fmaf(xv,wu1.z,aU1.z); aU1.w=fmaf(xv,wu1.w,aU1.w);
            aG1.x=fmaf(xv,wg1.x,aG1.x); aG1.y=fmaf(xv,wg1.y,aG1.y); aG1.z=fmaf(xv,wg1.z,aG1.z); aG1.w=fmaf(xv,wg1.w,aG1.w);
        }
        float4 h0, h1;
        h0.x=fmaxf(aG0.x,0.f)*aU0.x; h0.y=fmaxf(aG0.y,0.f)*aU0.y;
        h0.z=fmaxf(aG0.z,0.f)*aU0.z; h0.w=fmaxf(aG0.w,0.f)*aU0.w;
        h1.x=fmaxf(aG1.x,0.f)*aU1.x; h1.y=fmaxf(aG1.y,0.f)*aU1.y;
        h1.z=fmaxf(aG1.z,0.f)*aU1.z; h1.w=fmaxf(aG1.w,0.f)*aU1.w;
        ((float4*)hb)[tp*32+dq]=h0;
        ((float4*)hb)[tp*32+dq+16]=h1;
    }
    __syncthreads();
    {
        float4 acc=((float4*)db)[dq];
        const float* hr=hb+tp*128;
        #pragma unroll
        for (int k=0;k<128;k++){
            float xv=hr[k]; float4 w=((float4*)dw)[k*16+dq];
            acc.x=fmaf(xv,w.x,acc.x); acc.y=fmaf(xv,w.y,acc.y);
            acc.z=fmaf(xv,w.z,acc.z); acc.w=fmaf(xv,w.w,acc.w);
        }
        float4 f2=((float4*)fin2)[tp*16+dq];
        float4 f3;
        f3.x=f2.x+fmaxf(acc.x,0.f); f3.y=f2.y+fmaxf(acc.y,0.f);
        f3.z=f2.z+fmaxf(acc.z,0.f); f3.w=f2.w+fmaxf(acc.w,0.f);
        ((float4*)fin3)[tp*16+dq]=f3;
    }
    __syncthreads();
    {
        int w=t>>5, lane=t&31;
        int which=w&1, rb=w>>1;
        #pragma unroll
        for (int it=0; it<4; it++){
            int row=rb+it*8;
            int p=p0+row;
            int idx = which? negs[p] : poss[p];
            const float* er=emb+(size_t)idx*DD;
            const float* f3r=fin3+row*DD;
            float s=f3r[lane]*er[lane]+f3r[lane+32]*er[lane+32];
            #pragma unroll
            for (int o=16;o>0;o>>=1) s+=__shfl_xor_sync(0xffffffffu,s,o);
            if (lane==0) out[which*PP+p]=s;
        }
    }
}

// ---------------- host launcher ----------------
extern "C" void kernel_launch(void* const* d_in, const int* in_sizes, int n_in,
                              void* d_out, int out_size){
    const int*   logs = (const int*)  d_in[0];
    const int*   poss = (const int*)  d_in[1];
    const int*   negs = (const int*)  d_in[2];
    const float* adj  = (const float*)d_in[4];
    const float* emb  = (const float*)d_in[5];
    const float* pe   = (const float*)d_in[6];
    const float* Wi   = (const float*)d_in[7];
    const float* ai   = (const float*)d_in[8];
    const float* W1   = (const float*)d_in[9];
    const float* W2   = (const float*)d_in[10];
    const float* ba   = (const float*)d_in[11];
    const float* ccg  = (const float*)d_in[12];
    const float* cng  = (const float*)d_in[13];
    const float* c1w  = (const float*)d_in[14];
    const float* c1b  = (const float*)d_in[15];
    const float* c2w  = (const float*)d_in[16];
    const float* c2b  = (const float*)d_in[17];
    const float* uw   = (const float*)d_in[18];
    const float* ub   = (const float*)d_in[19];
    const float* gw   = (const float*)d_in[20];
    const float* gb   = (const float*)d_in[21];
    const float* dw   = (const float*)d_in[22];
    const float* db   = (const float*)d_in[23];
    float* out = (float*)d_out;

    cudaFuncSetAttribute(k2b_item, cudaFuncAttributeMaxDynamicSharedMemorySize, 98304);
    cudaFuncSetAttribute(k4_ffn,   cudaFuncAttributeMaxDynamicSharedMemorySize, 182016);

    k1_fused<<<208,512>>>(emb, Wi, ai, pe, W1, W2, logs);
    k2a_gat<<<N1,256>>>(adj);
    k2b_item<<<188,512,98304>>>(emb, ccg, cng, W1, W2);
    dim3 g3(7, BB);
    k3_attn<<<g3,256>>>(ba, logs);
    k4_ffn<<<200,512,182016>>>(poss, negs, emb, c1w,c1b,c2w,c2b, uw,ub,gw,gb, dw,db, out);
}

// round 5
// speedup vs baseline: 1.7806x; 1.0258x over previous
#include <cuda_runtime.h>
#include <math.h>

#define N1 6001
#define DD 64
#define LL 200
#define BB 32
#define PP 6400
#define MAXNZ 1024
#define RS 68   // k3 smem row stride in floats (272B, 16B-aligned, conflict-free)

// ---------------- device scratch (zero-initialized at load) ----------------
__device__ __align__(16) float g_h[N1*DD];
__device__ float g_wh1[N1];
__device__ float g_wh2[N1];
__device__ int   g_flags[N1];
__device__ __align__(16) float g_gat_i[N1*DD];
__device__ __align__(16) float g_trans_i[N1*DD];
__device__ __align__(16) float g_seqs_i[N1*DD];
__device__ __align__(16) float g_A1[N1*DD];
__device__ __align__(16) float g_A2[N1*DD];
__device__ __align__(16) float g_P1[LL*DD];
__device__ __align__(16) float g_P2[LL*DD];
__device__ __align__(16) float g_final[PP*DD];

__device__ __forceinline__ float mufu_rcp(float u){
    float r;
    asm("rcp.approx.f32 %0, %1;" : "=f"(r) : "f"(u));
    return r;
}
__device__ __forceinline__ void fma4(float4& a, float v, const float4& w){
    a.x=fmaf(v,w.x,a.x); a.y=fmaf(v,w.y,a.y); a.z=fmaf(v,w.z,a.z); a.w=fmaf(v,w.w,a.w);
}

// ============ K1 fused: hitem (bid<188, 32 rows) | pproj (188..194) | mark (195..219) ============
__global__ __launch_bounds__(256) void k1_fused(const float* __restrict__ emb,
        const float* __restrict__ Wi, const float* __restrict__ ai,
        const float* __restrict__ pe, const float* __restrict__ w1g,
        const float* __restrict__ w2g, const int* __restrict__ logs){
    __shared__ __align__(16) float Xs[2048];
    int t = threadIdx.x;
    int bid = blockIdx.x;
    if (bid >= 195){
        int p = (bid-195)*256 + t;
        g_flags[logs[p]] = 1;
        return;
    }
    if (bid < 188){
        int r0 = bid*32;
        for (int u=t; u<512; u+=256){
            int row=u>>4, col=u&15; int r=r0+row;
            float4 v = make_float4(0.f,0.f,0.f,0.f);
            if (r < N1) v = ((const float4*)emb)[r*16+col];
            ((float4*)Xs)[u] = v;
        }
        __syncthreads();
        int tp=t>>4, dq=t&15;
        float4 a0=make_float4(0.f,0.f,0.f,0.f), a1=a0;
        const float* x0=Xs+tp*64; const float* x1=Xs+(tp+16)*64;
        const float4* W4=(const float4*)Wi;
        #pragma unroll 8
        for (int k=0;k<64;k++){
            float4 w=__ldg(&W4[k*16+dq]);
            fma4(a0, x0[k], w);
            fma4(a1, x1[k], w);
        }
        int rA=r0+tp, rB=r0+tp+16;
        if (rA<N1) ((float4*)g_h)[rA*16+dq]=a0;
        if (rB<N1) ((float4*)g_h)[rB*16+dq]=a1;
        const float4* A4=(const float4*)ai;
        float4 v1=__ldg(&A4[dq]), v2=__ldg(&A4[16+dq]);
        float s1a=a0.x*v1.x+a0.y*v1.y+a0.z*v1.z+a0.w*v1.w;
        float s2a=a0.x*v2.x+a0.y*v2.y+a0.z*v2.z+a0.w*v2.w;
        float s1b=a1.x*v1.x+a1.y*v1.y+a1.z*v1.z+a1.w*v1.w;
        float s2b=a1.x*v2.x+a1.y*v2.y+a1.z*v2.z+a1.w*v2.w;
        #pragma unroll
        for (int o=8;o>0;o>>=1){
            s1a+=__shfl_xor_sync(0xffffffffu,s1a,o);
            s2a+=__shfl_xor_sync(0xffffffffu,s2a,o);
            s1b+=__shfl_xor_sync(0xffffffffu,s1b,o);
            s2b+=__shfl_xor_sync(0xffffffffu,s2b,o);
        }
        if (dq==0){
            if (rA<N1){ g_wh1[rA]=s1a; g_wh2[rA]=s2a; }
            if (rB<N1){ g_wh1[rB]=s1b; g_wh2[rB]=s2b; }
        }
        return;
    }
    // pproj
    {
        int l0=(bid-188)*32;
        for (int u=t; u<512; u+=256){
            int row=u>>4, col=u&15; int l=l0+row;
            float4 v = make_float4(0.f,0.f,0.f,0.f);
            if (l<LL) v = ((const float4*)pe)[l*16+col];
            ((float4*)Xs)[u]=v;
        }
        __syncthreads();
        int tp=t>>4, dq=t&15;
        float4 p1A=make_float4(0.f,0.f,0.f,0.f), p2A=p1A, p1B=p1A, p2B=p1A;
        const float* x0=Xs+tp*64; const float* x1=Xs+(tp+16)*64;
        const float4* W1=(const float4*)w1g; const float4* W2=(const float4*)w2g;
        #pragma unroll 8
        for (int k=0;k<64;k++){
            float4 w1=__ldg(&W1[k*16+dq]), w2=__ldg(&W2[k*16+dq]);
            float v0=x0[k], v1=x1[k];
            fma4(p1A,v0,w1); fma4(p2A,v0,w2);
            fma4(p1B,v1,w1); fma4(p2B,v1,w2);
        }
        int lA=l0+tp, lB=l0+tp+16;
        if (lA<LL){ ((float4*)g_P1)[lA*16+dq]=p1A; ((float4*)g_P2)[lA*16+dq]=p2A; }
        if (lB<LL){ ((float4*)g_P1)[lB*16+dq]=p1B; ((float4*)g_P2)[lB*16+dq]=p2B; }
    }
}

// ============ K2a: sparse GAT per UNIQUE item (self-resets flag) ============
__global__ void k2a_gat(const float* __restrict__ adj){
    __shared__ int   s_idx[MAXNZ];
    __shared__ float s_val[MAXNZ];
    __shared__ float s_e[MAXNZ];
    __shared__ int wsum[8]; __shared__ int woff[8]; __shared__ int s_n;
    __shared__ float wred[8];
    __shared__ float pg[4][DD], pt[4][DD];
    int i = blockIdx.x;
    if (g_flags[i]==0) return;
    int t=threadIdx.x, lane=t&31, w=t>>5;
    const float* row = adj + (size_t)i*(size_t)N1;
    int c=0;
    for (int j=t;j<N1;j+=256) c += (row[j]>0.f)?1:0;
    int sc=c;
    #pragma unroll
    for (int o=1;o<32;o<<=1){ int v=__shfl_up_sync(0xffffffffu,sc,o); if(lane>=o) sc+=v; }
    if (lane==31) wsum[w]=sc;
    __syncthreads();
    if (t<8){
        int v=wsum[t]; int iv=v;
        #pragma unroll
        for (int o=1;o<8;o<<=1){ int u=__shfl_up_sync(0x000000ffu,iv,o); if(t>=o) iv+=u; }
        woff[t]=iv-v;
        if (t==7) s_n=iv;
    }
    __syncthreads();
    int off = woff[w] + (sc - c);
    for (int j=t;j<N1;j+=256){
        float a=row[j];
        if (a>0.f){ if(off<MAXNZ){ s_idx[off]=j; s_val[off]=a; } off++; }
    }
    __syncthreads();
    int n = s_n; if (n>MAXNZ) n=MAXNZ;
    int d=t&63, g4=t>>6;
    if (n==0){
        float s=0.f;
        for (int r=g4; r<N1; r+=4) s += g_h[r*DD+d];
        pg[g4][d]=s;
        __syncthreads();
        if (t<DD){
            float mm=(pg[0][t]+pg[1][t]+pg[2][t]+pg[3][t])*(1.f/(float)N1);
            g_gat_i[i*DD+t]=mm; g_trans_i[i*DD+t]=0.f;
        }
        if (t==0) g_flags[i]=0;
        return;
    }
    float wh1i = g_wh1[i];
    float m=-1e30f;
    for (int k=t;k<n;k+=256){
        float e = wh1i + g_wh2[s_idx[k]];
        e = (e>0.f)? e : 0.01f*e;
        s_e[k]=e;
        m = fmaxf(m,e);
    }
    #pragma unroll
    for (int o=16;o>0;o>>=1) m=fmaxf(m,__shfl_xor_sync(0xffffffffu,m,o));
    if (lane==0) wred[w]=m;
    __syncthreads();
    float M=wred[0];
    #pragma unroll
    for (int k=1;k<8;k++) M=fmaxf(M,wred[k]);
    __syncthreads();
    float ds=0.f;
    for (int k=t;k<n;k+=256){
        float wv=__expf(s_e[k]-M);
        s_e[k]=wv; ds+=wv;
    }
    #pragma unroll
    for (int o=16;o>0;o>>=1) ds += __shfl_xor_sync(0xffffffffu,ds,o);
    if (lane==0) wred[w]=ds;
    __syncthreads();
    float den=0.f;
    #pragma unroll
    for (int k=0;k<8;k++) den+=wred[k];
    float ga=0.f, ta=0.f;
    for (int k=g4;k<n;k+=4){
        float hv = g_h[s_idx[k]*DD+d];
        ga = fmaf(s_e[k],hv,ga);
        ta = fmaf(s_val[k],hv,ta);
    }
    pg[g4][d]=ga; pt[g4][d]=ta;
    __syncthreads();
    if (t<DD){
        float gg=(pg[0][t]+pg[1][t])+(pg[2][t]+pg[3][t]);
        float tt=(pt[0][t]+pt[1][t])+(pt[2][t]+pt[3][t]);
        float rden = mufu_rcp(den);
        g_gat_i[i*DD+t]=gg*rden; g_trans_i[i*DD+t]=tt;
    }
    if (t==0) g_flags[i]=0;
}

// ============ K2b_item: per-item coff/seqs + A1/A2 (256 thr, 32 rows, R=2, L1 weights) ============
__global__ __launch_bounds__(256) void k2b_item(const float* __restrict__ emb,
        const float* __restrict__ ccg, const float* __restrict__ cng,
        const float* __restrict__ w1g, const float* __restrict__ w2g){
    __shared__ __align__(16) float Xg[2048], Xt[2048], Xe[2048], X2[2048];
    int t=threadIdx.x;
    int r0=blockIdx.x*32;
    for (int u=t; u<512; u+=256){
        int row=u>>4, col=u&15; int r=r0+row;
        float4 g=make_float4(0.f,0.f,0.f,0.f), tv=g, e=g;
        if (r<N1){
            g =((float4*)g_gat_i)[r*16+col];
            tv=((float4*)g_trans_i)[r*16+col];
            e =((const float4*)emb)[r*16+col];
        }
        ((float4*)Xg)[u]=g; ((float4*)Xt)[u]=tv; ((float4*)Xe)[u]=e;
    }
    __syncthreads();
    int tp=t>>4, dq=t&15;
    float4 xA=make_float4(0.f,0.f,0.f,0.f), xB=xA;
    const float* g0=Xg+tp*64; const float* t0=Xt+tp*64;
    const float* g1=Xg+(tp+16)*64; const float* t1=Xt+(tp+16)*64;
    const float4* CC=(const float4*)ccg; const float4* CN=(const float4*)cng;
    #pragma unroll 8
    for (int k=0;k<64;k++){
        float4 c1=__ldg(&CC[k*16+dq]), c2=__ldg(&CN[k*16+dq]);
        fma4(xA,g0[k],c1); fma4(xA,t0[k],c2);
        fma4(xB,g1[k],c1); fma4(xB,t1[k],c2);
    }
    float4 cfA, cfB;
    cfA.x=mufu_rcp(1.f+__expf(-xA.x)); cfA.y=mufu_rcp(1.f+__expf(-xA.y));
    cfA.z=mufu_rcp(1.f+__expf(-xA.z)); cfA.w=mufu_rcp(1.f+__expf(-xA.w));
    cfB.x=mufu_rcp(1.f+__expf(-xB.x)); cfB.y=mufu_rcp(1.f+__expf(-xB.y));
    cfB.z=mufu_rcp(1.f+__expf(-xB.z)); cfB.w=mufu_rcp(1.f+__expf(-xB.w));
    float4 gA=((float4*)Xg)[tp*16+dq], tA4=((float4*)Xt)[tp*16+dq], eA=((float4*)Xe)[tp*16+dq];
    float4 gB=((float4*)Xg)[(tp+16)*16+dq], tB4=((float4*)Xt)[(tp+16)*16+dq], eB=((float4*)Xe)[(tp+16)*16+dq];
    float4 svA, svB;
    svA.x=cfA.x*gA.x+(1.f-cfA.x)*tA4.x+eA.x;
    svA.y=cfA.y*gA.y+(1.f-cfA.y)*tA4.y+eA.y;
    svA.z=cfA.z*gA.z+(1.f-cfA.z)*tA4.z+eA.z;
    svA.w=cfA.w*gA.w+(1.f-cfA.w)*tA4.w+eA.w;
    svB.x=cfB.x*gB.x+(1.f-cfB.x)*tB4.x+eB.x;
    svB.y=cfB.y*gB.y+(1.f-cfB.y)*tB4.y+eB.y;
    svB.z=cfB.z*gB.z+(1.f-cfB.z)*tB4.z+eB.z;
    svB.w=cfB.w*gB.w+(1.f-cfB.w)*tB4.w+eB.w;
    ((float4*)X2)[tp*16+dq]=svA;
    ((float4*)X2)[(tp+16)*16+dq]=svB;
    int rA=r0+tp, rB=r0+tp+16;
    if (rA<N1) ((float4*)g_seqs_i)[rA*16+dq]=svA;
    if (rB<N1) ((float4*)g_seqs_i)[rB*16+dq]=svB;
    __syncthreads();
    float4 a1A=make_float4(0.f,0.f,0.f,0.f), a2A=a1A, a1B=a1A, a2B=a1A;
    const float* xr0=X2+tp*64; const float* xr1=X2+(tp+16)*64;
    const float4* W1=(const float4*)w1g; const float4* W2=(const float4*)w2g;
    #pragma unroll 8
    for (int k=0;k<64;k++){
        float4 w1=__ldg(&W1[k*16+dq]), w2=__ldg(&W2[k*16+dq]);
        float v0=xr0[k], v1=xr1[k];
        fma4(a1A,v0,w1); fma4(a2A,v0,w2);
        fma4(a1B,v1,w1); fma4(a2B,v1,w2);
    }
    if (rA<N1){ ((float4*)g_A1)[rA*16+dq]=a1A; ((float4*)g_A2)[rA*16+dq]=a2A; }
    if (rB<N1){ ((float4*)g_A1)[rB*16+dq]=a1B; ((float4*)g_A2)[rB*16+dq]=a2B; }
}

// ============ K3: mirrored-pair causal attention, QT=8, 2 q-rows/thread ============
// grid (13, 32): pair p -> tiles (p, 24-p); p==12 self (tileB disabled).
__global__ __launch_bounds__(256,4) void k3_attn(const float* __restrict__ ba,
                                                 const int* __restrict__ logs){
    __shared__ __align__(16) float E1s[16*RS];
    __shared__ __align__(16) float E2c[32*RS];
    __shared__ __align__(16) float Sc[32*RS];
    __shared__ __align__(16) float bsS[64];
    __shared__ float scc[16*36];
    __shared__ int litem[32];
    int t=threadIdx.x, bb=blockIdx.y, p=blockIdx.x;
    bool hasB = (p!=12);
    int kendMax = 200 - 8*p;
    if (t<16) ((float4*)bsS)[t]=__ldg(((const float4*)ba)+t);
    // E1 staging: 16 rows (0-7 tileA, 8-15 tileB)
    {
        int r=t>>4, col=t&15;
        bool ok = (r<8) || hasB;
        if (ok){
            int q = (r<8)? (8*p+r) : (192-8*p + (r-8));
            int iq = logs[bb*LL+q];
            float m=(iq!=0)?1.f:0.f;
            float4 a=((const float4*)g_A1)[(size_t)iq*16+col];
            float4 pq=((const float4*)g_P1)[(size_t)q*16+col];
            float4 e;
            e.x=__expf(-fmaf(m,pq.x,a.x));
            e.y=__expf(-fmaf(m,pq.y,a.y));
            e.z=__expf(-fmaf(m,pq.z,a.z));
            e.w=__expf(-fmaf(m,pq.w,a.w));
            *(float4*)(E1s + r*RS + col*4) = e;
        }
    }
    __syncthreads();
    int w=t>>5, l=t&31;
    int qA = 8*p + w;
    int qB = 192 - 8*p + w;
    float2 aA=make_float2(0.f,0.f), aB=aA;
    for (int kbase=0; kbase<kendMax; kbase+=32){
        int rows = kendMax-kbase; if (rows>32) rows=32;
        if (t<rows) litem[t]=logs[bb*LL+kbase+t];
        __syncthreads();
        for (int u=t; u<rows*16; u+=256){
            int r=u>>4, col=u&15;
            int it=litem[r];
            int ll=kbase+r;
            float m=(it!=0)?1.f:0.f;
            float4 a=((const float4*)g_A2)[(size_t)it*16+col];
            float4 pq=((const float4*)g_P2)[(size_t)ll*16+col];
            float4 e;
            e.x=__expf(-fmaf(m,pq.x,a.x));
            e.y=__expf(-fmaf(m,pq.y,a.y));
            e.z=__expf(-fmaf(m,pq.z,a.z));
            e.w=__expf(-fmaf(m,pq.w,a.w));
            *(float4*)(E2c + r*RS + col*4) = e;
            *(float4*)(Sc  + r*RS + col*4) = ((const float4*)g_seqs_i)[(size_t)it*16+col];
        }
        __syncthreads();
        // ---- phase B: scores ----
        {
            bool doA = (kbase <= qA);
            bool doB = hasB;  // qB >= any kbase in range
            int kk=kbase+l;
            bool inA = doA && (l<rows) && (kk<=qA);
            bool inB = doB && (l<rows) && (kk<=qB);
            float accA=0.f, accB=0.f;
            const float4* e2p=(const float4*)(E2c + l*RS);
            const float4* bp=(const float4*)bsS;
            if (doA && doB){
                const float4* eAp=(const float4*)(E1s + w*RS);
                const float4* eBp=(const float4*)(E1s + (w+8)*RS);
                #pragma unroll
                for (int j=0;j<16;j++){
                    float4 e=e2p[j], b=bp[j], a=eAp[j], c=eBp[j];
                    accA=fmaf(b.x, mufu_rcp(fmaf(a.x,e.x,1.f)), accA);
                    accB=fmaf(b.x, mufu_rcp(fmaf(c.x,e.x,1.f)), accB);
                    accA=fmaf(b.y, mufu_rcp(fmaf(a.y,e.y,1.f)), accA);
                    accB=fmaf(b.y, mufu_rcp(fmaf(c.y,e.y,1.f)), accB);
                    accA=fmaf(b.z, mufu_rcp(fmaf(a.z,e.z,1.f)), accA);
                    accB=fmaf(b.z, mufu_rcp(fmaf(c.z,e.z,1.f)), accB);
                    accA=fmaf(b.w, mufu_rcp(fmaf(a.w,e.w,1.f)), accA);
                    accB=fmaf(b.w, mufu_rcp(fmaf(c.w,e.w,1.f)), accB);
                }
            } else if (doB){
                const float4* eBp=(const float4*)(E1s + (w+8)*RS);
                #pragma unroll
                for (int j=0;j<16;j++){
                    float4 e=e2p[j], b=bp[j], c=eBp[j];
                    accB=fmaf(b.x, mufu_rcp(fmaf(c.x,e.x,1.f)), accB);
                    accB=fmaf(b.y, mufu_rcp(fmaf(c.y,e.y,1.f)), accB);
                    accB=fmaf(b.z, mufu_rcp(fmaf(c.z,e.z,1.f)), accB);
                    accB=fmaf(b.w, mufu_rcp(fmaf(c.w,e.w,1.f)), accB);
                }
            } else if (doA){
                const float4* eAp=(const float4*)(E1s + w*RS);
                #pragma unroll
                for (int j=0;j<16;j++){
                    float4 e=e2p[j], b=bp[j], a=eAp[j];
                    accA=fmaf(b.x, mufu_rcp(fmaf(a.x,e.x,1.f)), accA);
                    accA=fmaf(b.y, mufu_rcp(fmaf(a.y,e.y,1.f)), accA);
                    accA=fmaf(b.z, mufu_rcp(fmaf(a.z,e.z,1.f)), accA);
                    accA=fmaf(b.w, mufu_rcp(fmaf(a.w,e.w,1.f)), accA);
                }
            }
            if (inA) scc[w*36+l]=accA;
            if (inB) scc[(w+8)*36+l]=accB;
        }
        __syncthreads();
        // ---- phase C: accumulate final (2 rows per thread, shared Sc read) ----
        {
            int klA = qA - kbase + 1; if (klA<0) klA=0; if (klA>rows) klA=rows;
            int klB = hasB? (qB - kbase + 1) : 0; if (klB>rows) klB=rows;
            const float* sA=scc + w*36;
            const float* sB=scc + (w+8)*36;
            int kl=0;
            for (; kl<klA; kl++){
                float2 s=*(const float2*)(Sc + kl*RS + l*2);
                float va=sA[kl], vb=sB[kl];
                aA.x=fmaf(va,s.x,aA.x); aA.y=fmaf(va,s.y,aA.y);
                aB.x=fmaf(vb,s.x,aB.x); aB.y=fmaf(vb,s.y,aB.y);
            }
            for (; kl<klB; kl++){
                float2 s=*(const float2*)(Sc + kl*RS + l*2);
                float vb=sB[kl];
                aB.x=fmaf(vb,s.x,aB.x); aB.y=fmaf(vb,s.y,aB.y);
            }
        }
        __syncthreads();
    }
    *(float2*)(g_final + (size_t)(bb*LL+qA)*64 + l*2) = aA;
    if (hasB) *(float2*)(g_final + (size_t)(bb*LL+qB)*64 + l*2) = aB;
}

// ============ K4: FFN + UpDown + logits (256 thr, 32 rows, L1 weights) ============
__global__ __launch_bounds__(256,4) void k4_ffn(const int* __restrict__ poss,
        const int* __restrict__ negs, const float* __restrict__ emb,
        const float* __restrict__ c1wg,const float* __restrict__ c1bg,
        const float* __restrict__ c2wg,const float* __restrict__ c2bg,
        const float* __restrict__ uwg,const float* __restrict__ ubg,
        const float* __restrict__ gwg,const float* __restrict__ gbg,
        const float* __restrict__ dwg,const float* __restrict__ dbg,
        float* __restrict__ out){
    __shared__ __align__(16) float fin[2048], f1[2048], fin2[2048], hb[4096], fin3[2048];
    int t=threadIdx.x;
    int p0=blockIdx.x*32;
    for (int u=t; u<512; u+=256)
        ((float4*)fin)[u]=((float4*)g_final)[(size_t)p0*16+u];
    __syncthreads();
    int tp=t>>4, dq=t&15;
    // stage 1: f1 = relu(fin@c1w + c1b)
    {
        float4 b=__ldg(((const float4*)c1bg)+dq);
        float4 a0=b, a1=b;
        const float* x0=fin+tp*64; const float* x1=fin+(tp+16)*64;
        const float4* W=(const float4*)c1wg;
        #pragma unroll 8
        for (int k=0;k<64;k++){
            float4 w=__ldg(&W[k*16+dq]);
            fma4(a0,x0[k],w); fma4(a1,x1[k],w);
        }
        a0.x=fmaxf(a0.x,0.f); a0.y=fmaxf(a0.y,0.f); a0.z=fmaxf(a0.z,0.f); a0.w=fmaxf(a0.w,0.f);
        a1.x=fmaxf(a1.x,0.f); a1.y=fmaxf(a1.y,0.f); a1.z=fmaxf(a1.z,0.f); a1.w=fmaxf(a1.w,0.f);
        ((float4*)f1)[tp*16+dq]=a0;
        ((float4*)f1)[(tp+16)*16+dq]=a1;
    }
    __syncthreads();
    // stage 2: fin2 = fin + f1@c2w + c2b
    {
        float4 b=__ldg(((const float4*)c2bg)+dq);
        float4 a0=b, a1=b;
        const float* x0=f1+tp*64; const float* x1=f1+(tp+16)*64;
        const float4* W=(const float4*)c2wg;
        #pragma unroll 8
        for (int k=0;k<64;k++){
            float4 w=__ldg(&W[k*16+dq]);
            fma4(a0,x0[k],w); fma4(a1,x1[k],w);
        }
        float4 fA=((float4*)fin)[tp*16+dq], fB=((float4*)fin)[(tp+16)*16+dq];
        a0.x+=fA.x; a0.y+=fA.y; a0.z+=fA.z; a0.w+=fA.w;
        a1.x+=fB.x; a1.y+=fB.y; a1.z+=fB.z; a1.w+=fB.w;
        ((float4*)fin2)[tp*16+dq]=a0;
        ((float4*)fin2)[(tp+16)*16+dq]=a1;
    }
    __syncthreads();
    // stage 3: hb = relu(fin2@gw+gb) * (fin2@uw+ub); 32 f4-cols x 8 row-groups, R=4
    {
        int rp=t>>5, dz=t&31;
        float4 ub4=__ldg(((const float4*)ubg)+dz);
        float4 gb4=__ldg(((const float4*)gbg)+dz);
        float4 aU[4], aG[4];
        #pragma unroll
        for (int j=0;j<4;j++){ aU[j]=ub4; aG[j]=gb4; }
        const float4* U=(const float4*)uwg; const float4* G=(const float4*)gwg;
        #pragma unroll 4
        for (int k=0;k<64;k++){
            float4 wu=__ldg(&U[k*32+dz]), wg=__ldg(&G[k*32+dz]);
            #pragma unroll
            for (int j=0;j<4;j++){
                float xv=fin2[(rp+8*j)*64+k];
                fma4(aU[j],xv,wu); fma4(aG[j],xv,wg);
            }
        }
        #pragma unroll
        for (int j=0;j<4;j++){
            float4 h;
            h.x=fmaxf(aG[j].x,0.f)*aU[j].x; h.y=fmaxf(aG[j].y,0.f)*aU[j].y;
            h.z=fmaxf(aG[j].z,0.f)*aU[j].z; h.w=fmaxf(aG[j].w,0.f)*aU[j].w;
            ((float4*)hb)[(rp+8*j)*32+dz]=h;
        }
    }
    __syncthreads();
    // stage 4: fin3 = fin2 + relu(hb@dw + db)
    {
        float4 b=__ldg(((const float4*)dbg)+dq);
        float4 a0=b, a1=b;
        const float* h0=hb+tp*128; const float* h1=hb+(tp+16)*128;
        const float4* W=(const float4*)dwg;
        #pragma unroll 8
        for (int k=0;k<128;k++){
            float4 w=__ldg(&W[k*16+dq]);
            fma4(a0,h0[k],w); fma4(a1,h1[k],w);
        }
        float4 fA=((float4*)fin2)[tp*16+dq], fB=((float4*)fin2)[(tp+16)*16+dq];
        float4 o0, o1;
        o0.x=fA.x+fmaxf(a0.x,0.f); o0.y=fA.y+fmaxf(a0.y,0.f);
        o0.z=fA.z+fmaxf(a0.z,0.f); o0.w=fA.w+fmaxf(a0.w,0.f);
        o1.x=fB.x+fmaxf(a1.x,0.f); o1.y=fB.y+fmaxf(a1.y,0.f);
        o1.z=fB.z+fmaxf(a1.z,0.f); o1.w=fB.w+fmaxf(a1.w,0.f);
        ((float4*)fin3)[tp*16+dq]=o0;
        ((float4*)fin3)[(tp+16)*16+dq]=o1;
    }
    __syncthreads();
    // logits: 8 warps x 8 tasks = 32 rows x {pos,neg}
    {
        int w=t>>5, lane=t&31;
        #pragma unroll
        for (int it=0; it<8; it++){
            int task=w*8+it;
            int which=task&1, row=task>>1;
            int pidx=p0+row;
            int idx = which? negs[pidx] : poss[pidx];
            const float* er=emb+(size_t)idx*64;
            const float* fr=fin3+row*64;
            float s=fr[lane]*er[lane]+fr[lane+32]*er[lane+32];
            #pragma unroll
            for (int o=16;o>0;o>>=1) s+=__shfl_xor_sync(0xffffffffu,s,o);
            if (lane==0) out[which*PP+pidx]=s;
        }
    }
}

// ---------------- host launcher ----------------
extern "C" void kernel_launch(void* const* d_in, const int* in_sizes, int n_in,
                              void* d_out, int out_size){
    const int*   logs = (const int*)  d_in[0];
    const int*   poss = (const int*)  d_in[1];
    const int*   negs = (const int*)  d_in[2];
    const float* adj  = (const float*)d_in[4];
    const float* emb  = (const float*)d_in[5];
    const float* pe   = (const float*)d_in[6];
    const float* Wi   = (const float*)d_in[7];
    const float* ai   = (const float*)d_in[8];
    const float* W1   = (const float*)d_in[9];
    const float* W2   = (const float*)d_in[10];
    const float* ba   = (const float*)d_in[11];
    const float* ccg  = (const float*)d_in[12];
    const float* cng  = (const float*)d_in[13];
    const float* c1w  = (const float*)d_in[14];
    const float* c1b  = (const float*)d_in[15];
    const float* c2w  = (const float*)d_in[16];
    const float* c2b  = (const float*)d_in[17];
    const float* uw   = (const float*)d_in[18];
    const float* ub   = (const float*)d_in[19];
    const float* gw   = (const float*)d_in[20];
    const float* gb   = (const float*)d_in[21];
    const float* dw   = (const float*)d_in[22];
    const float* db   = (const float*)d_in[23];
    float* out = (float*)d_out;

    k1_fused<<<220,256>>>(emb, Wi, ai, pe, W1, W2, logs);
    k2a_gat<<<N1,256>>>(adj);
    k2b_item<<<188,256>>>(emb, ccg, cng, W1, W2);
    dim3 g3(13, BB);
    k3_attn<<<g3,256>>>(ba, logs);
    k4_ffn<<<200,256>>>(poss, negs, emb, c1w,c1b,c2w,c2b, uw,ub,gw,gb, dw,db, out);
}